// round 3
// baseline (speedup 1.0000x reference)
#include <cuda_runtime.h>
#include <math.h>
#include <stdint.h>

#define BN   256      // batch
#define PN   32768    // proxies
#define DN   256      // feature dim
#define CN   8        // cameras
#define KSCALE 20.0f  // 1/TEMP
#define BGK  50
#define PKK  3
#define BALW 0.15f

#define NEG_INF (__int_as_float(0xff800000))

// ---------------- scratch ----------------
__device__ float g_A[2 * BN * DN];
__device__ int   g_pseudo[BN];
__device__ float g_inputs[(size_t)BN * PN];    // 32 MB
__device__ float g_sims[(size_t)BN * PN];      // 32 MB
__device__ float g_loss[3 * BN];

__device__ __forceinline__ unsigned fkey(float v) {
    unsigned u = __float_as_uint(v);
    return (u & 0x80000000u) ? ~u : (u | 0x80000000u);
}
__device__ __forceinline__ float unfkey(unsigned k) {
    unsigned u = (k & 0x80000000u) ? (k ^ 0x80000000u) : ~k;
    return __uint_as_float(u);
}

// block reductions via warp shuffle + 16-slot shared merge (no per-element atomics)
__device__ __forceinline__ float blockMaxF(float x, float* s16, int t) {
    int lane = t & 31, wid = t >> 5;
    for (int o = 16; o > 0; o >>= 1) x = fmaxf(x, __shfl_down_sync(0xffffffffu, x, o));
    __syncthreads();
    if (lane == 0) s16[wid] = x;
    __syncthreads();
    if (t == 0) { float y = s16[0]; for (int w = 1; w < 16; w++) y = fmaxf(y, s16[w]); s16[0] = y; }
    __syncthreads();
    return s16[0];
}
__device__ __forceinline__ float blockSumF(float x, float* s16, int t) {
    int lane = t & 31, wid = t >> 5;
    for (int o = 16; o > 0; o >>= 1) x += __shfl_down_sync(0xffffffffu, x, o);
    __syncthreads();
    if (lane == 0) s16[wid] = x;
    __syncthreads();
    if (t == 0) { float y = 0.f; for (int w = 0; w < 16; w++) y += s16[w]; s16[0] = y; }
    __syncthreads();
    return s16[0];
}
__device__ __forceinline__ int blockSumI(int x, int* s16, int t) {
    int lane = t & 31, wid = t >> 5;
    for (int o = 16; o > 0; o >>= 1) x += __shfl_down_sync(0xffffffffu, x, o);
    __syncthreads();
    if (lane == 0) s16[wid] = x;
    __syncthreads();
    if (t == 0) { int y = 0; for (int w = 0; w < 16; w++) y += s16[w]; s16[0] = y; }
    __syncthreads();
    return s16[0];
}

// ---------------- K1: gather prx rows ----------------
__global__ void k_prep(const float* __restrict__ features,
                       const int* __restrict__ targets,
                       const int* __restrict__ all_proxy_label,
                       const float* __restrict__ mem) {
    int b = blockIdx.x;
    int t = threadIdx.x;
    int tgt = targets[b];
    int prx = all_proxy_label[tgt];
    if (t == 0) { g_pseudo[b] = prx / CN; }
    g_A[b * DN + t]        = features[b * DN + t];
    g_A[(BN + b) * DN + t] = mem[(size_t)prx * DN + t];
}

// ---------------- K2: fused dual GEMM (unchanged, proven) ----------------
__global__ __launch_bounds__(256, 2) void k_gemm(const float* __restrict__ mem) {
    __shared__ float sAf[16][65];
    __shared__ float sAp[16][65];
    __shared__ float sB[16][132];

    const int t  = threadIdx.x;
    const int tx = t & 15;
    const int ty = t >> 4;
    const int p0 = blockIdx.x * 128;
    const int b0 = blockIdx.y * 64;

    float accF[4][8];
    float accP[4][8];
#pragma unroll
    for (int i = 0; i < 4; i++)
#pragma unroll
        for (int j = 0; j < 8; j++) { accF[i][j] = 0.f; accP[i][j] = 0.f; }

    const int ar  = t >> 2;
    const int akc = (t & 3) << 2;
    const float* gAf = g_A + (size_t)(b0 + ar) * DN + akc;
    const float* gAp = g_A + (size_t)(BN + b0 + ar) * DN + akc;

    for (int k0 = 0; k0 < DN; k0 += 16) {
        float4 va = *(const float4*)(gAf + k0);
        float4 vp = *(const float4*)(gAp + k0);
        sAf[akc + 0][ar] = va.x; sAf[akc + 1][ar] = va.y;
        sAf[akc + 2][ar] = va.z; sAf[akc + 3][ar] = va.w;
        sAp[akc + 0][ar] = vp.x; sAp[akc + 1][ar] = vp.y;
        sAp[akc + 2][ar] = vp.z; sAp[akc + 3][ar] = vp.w;
#pragma unroll
        for (int s = 0; s < 2; s++) {
            int idx = t + 256 * s;
            int r   = idx >> 2;
            int kc  = (idx & 3) << 2;
            float4 vb = *(const float4*)(mem + (size_t)(p0 + r) * DN + k0 + kc);
            sB[kc + 0][r] = vb.x; sB[kc + 1][r] = vb.y;
            sB[kc + 2][r] = vb.z; sB[kc + 3][r] = vb.w;
        }
        __syncthreads();
#pragma unroll
        for (int kk = 0; kk < 16; kk++) {
            float af[4], ap[4], bb[8];
#pragma unroll
            for (int i = 0; i < 4; i++) {
                af[i] = sAf[kk][ty * 4 + i];
                ap[i] = sAp[kk][ty * 4 + i];
            }
            float4 b0v = *(const float4*)&sB[kk][tx * 4];
            float4 b1v = *(const float4*)&sB[kk][64 + tx * 4];
            bb[0] = b0v.x; bb[1] = b0v.y; bb[2] = b0v.z; bb[3] = b0v.w;
            bb[4] = b1v.x; bb[5] = b1v.y; bb[6] = b1v.z; bb[7] = b1v.w;
#pragma unroll
            for (int i = 0; i < 4; i++)
#pragma unroll
                for (int j = 0; j < 8; j++) {
                    accF[i][j] = fmaf(af[i], bb[j], accF[i][j]);
                    accP[i][j] = fmaf(ap[i], bb[j], accP[i][j]);
                }
        }
        __syncthreads();
    }

#pragma unroll
    for (int i = 0; i < 4; i++) {
        int b = b0 + ty * 4 + i;
        float* rin = g_inputs + (size_t)b * PN + p0;
        float* rsm = g_sims   + (size_t)b * PN + p0;
        float4 o;
        o.x = KSCALE * accF[i][0]; o.y = KSCALE * accF[i][1];
        o.z = KSCALE * accF[i][2]; o.w = KSCALE * accF[i][3];
        *(float4*)(rin + tx * 4) = o;
        o.x = KSCALE * accF[i][4]; o.y = KSCALE * accF[i][5];
        o.z = KSCALE * accF[i][6]; o.w = KSCALE * accF[i][7];
        *(float4*)(rin + 64 + tx * 4) = o;
        o.x = BALW * accF[i][0] + (1.0f - BALW) * accP[i][0];
        o.y = BALW * accF[i][1] + (1.0f - BALW) * accP[i][1];
        o.z = BALW * accF[i][2] + (1.0f - BALW) * accP[i][2];
        o.w = BALW * accF[i][3] + (1.0f - BALW) * accP[i][3];
        *(float4*)(rsm + tx * 4) = o;
        o.x = BALW * accF[i][4] + (1.0f - BALW) * accP[i][4];
        o.y = BALW * accF[i][5] + (1.0f - BALW) * accP[i][5];
        o.z = BALW * accF[i][6] + (1.0f - BALW) * accP[i][6];
        o.w = BALW * accF[i][7] + (1.0f - BALW) * accP[i][7];
        *(float4*)(rsm + 64 + tx * 4) = o;
    }
}

// ---------------- K3: intra + cross (register-resident, bisection top-k) ----
__global__ __launch_bounds__(512) void k_lossA(const int* __restrict__ cams) {
    __shared__ float s16[16];
    __shared__ int   si16[16];
    __shared__ float candv[512];
    __shared__ float sposv[8];
    __shared__ unsigned sh_cnt;

    const int b = blockIdx.x, t = threadIdx.x;
    const float* ri = g_inputs + (size_t)b * PN;
    const int pseudo = g_pseudo[b];
    const int cam = cams[b];

    if (t == 0) sh_cnt = 0;
    if (t < 8) sposv[t] = ri[pseudo * 8 + t];

    // ---- load 64 values into registers ----
    float v[64];
    float vcam[8];
    unsigned long long ex = 0ull;
#pragma unroll
    for (int i = 0; i < 8; i++) {
        int chunk = t + 512 * i;
        const float4* p4 = (const float4*)(ri + 8 * chunk);
        float4 a = p4[0], c = p4[1];
        v[i*8+0]=a.x; v[i*8+1]=a.y; v[i*8+2]=a.z; v[i*8+3]=a.w;
        v[i*8+4]=c.x; v[i*8+5]=c.y; v[i*8+6]=c.z; v[i*8+7]=c.w;
        float sel = (cam < 4) ? ((cam < 2) ? (cam == 0 ? a.x : a.y)
                                           : (cam == 2 ? a.z : a.w))
                              : ((cam < 6) ? (cam == 4 ? c.x : c.y)
                                           : (cam == 6 ? c.z : c.w));
        vcam[i] = sel;
        if (chunk == pseudo) ex |= (0xFFull << (i * 8));
    }

    // ---- maxes ----
    float m = NEG_INF, mi = NEG_INF;
#pragma unroll
    for (int s = 0; s < 64; s++) m = fmaxf(m, ((ex >> s) & 1ull) ? NEG_INF : v[s]);
#pragma unroll
    for (int i = 0; i < 8; i++) mi = fmaxf(mi, vcam[i]);
    float Mex = blockMaxF(m, s16, t);
    float Mi  = blockMaxF(mi, s16, t);
    __syncthreads();           // sposv visible everywhere
    float M = Mex;
#pragma unroll
    for (int k = 0; k < 8; k++) M = fmaxf(M, sposv[k]);

    // ---- bisection on key space for exact top-BGK pivot ----
    unsigned klo = 0u, khi = fkey(M);
    int C = PN;                // cnt(v > unfkey(klo)), upper bound
    for (int iter = 0; iter < 40; iter++) {
        if (C <= 400 || khi - klo <= 1u) break;
        unsigned mid = klo + ((khi - klo) >> 1);
        float pm = unfkey(mid);
        int c = 0;
#pragma unroll
        for (int s = 0; s < 64; s++)
            c += (!((ex >> s) & 1ull) && (v[s] > pm)) ? 1 : 0;
        int tot = blockSumI(c, si16, t);
        if (tot >= BGK) { klo = mid; C = tot; }
        else             khi = mid;
    }
    float pf = unfkey(klo);

    // ---- gather candidates (C in [50, ~400+dups]) ----
    __syncthreads();
#pragma unroll
    for (int s = 0; s < 64; s++) {
        if (!((ex >> s) & 1ull) && (v[s] > pf)) {
            unsigned k = atomicAdd(&sh_cnt, 1u);
            if (k < 512u) candv[k] = v[s];
        }
    }
    __syncthreads();
    int nc = (int)min(sh_cnt, 512u);

    // ---- exact rank: keep top BGK ----
    float seC = 0.f;
    for (int i = t; i < nc; i += 512) {
        float x = candv[i];
        int r = 0;
        for (int j = 0; j < nc; j++) {
            float w = candv[j];
            r += (w > x) || (w == x && j < i);
        }
        if (r < BGK) seC += __expf(x - M);
    }
    if (t < 8) seC += __expf(sposv[t] - M);
    float sumC = blockSumF(seC, s16, t);

    float seI = 0.f;
#pragma unroll
    for (int i = 0; i < 8; i++) seI += __expf(vcam[i] - Mi);
    float sumI = blockSumF(seI, s16, t);

    if (t == 0) {
        float psum = 0.f;
        for (int k = 0; k < 8; k++) psum += sposv[k];
        g_loss[b]      = Mi + logf(sumI) - sposv[cam];
        g_loss[BN + b] = M  + logf(sumC) - psum * 0.125f;
    }
}

// ---------------- K4: online (register-resident, bisection top-k) ----------
__global__ __launch_bounds__(512) void k_lossB() {
    __shared__ float s16[16];
    __shared__ int   si16[16];
    __shared__ float candv[512];
    __shared__ int   candi[512];
    __shared__ float s_cv[8][16];
    __shared__ int   s_ci[8][16];
    __shared__ int   chos[3];
    __shared__ int   fin[64];
    __shared__ unsigned sh_cnt, sh_nf;
    __shared__ float red[512];

    const int b = blockIdx.x, t = threadIdx.x;
    const int lane = t & 31, wid = t >> 5;
    const float* rs = g_sims   + (size_t)b * PN;
    const float* ri = g_inputs + (size_t)b * PN;

    if (t == 0) { sh_cnt = 0; sh_nf = 3; }

    // ---- load 64 sims values; per-camera (j) running argmax ----
    float v[64];
    float bv[8]; int bi[8];
#pragma unroll
    for (int j = 0; j < 8; j++) { bv[j] = NEG_INF; bi[j] = 0x7fffffff; }
#pragma unroll
    for (int i = 0; i < 8; i++) {
        int chunk = t + 512 * i;
        const float4* p4 = (const float4*)(rs + 8 * chunk);
        float4 a = p4[0], c = p4[1];
        v[i*8+0]=a.x; v[i*8+1]=a.y; v[i*8+2]=a.z; v[i*8+3]=a.w;
        v[i*8+4]=c.x; v[i*8+5]=c.y; v[i*8+6]=c.z; v[i*8+7]=c.w;
#pragma unroll
        for (int j = 0; j < 8; j++) {
            float x = v[i*8+j];
            if (x > bv[j]) { bv[j] = x; bi[j] = 8 * chunk + j; }
        }
    }

    // ---- per-camera warp reduce (value desc, index asc tie) ----
#pragma unroll
    for (int j = 0; j < 8; j++) {
        float x = bv[j]; int idx = bi[j];
        for (int o = 16; o > 0; o >>= 1) {
            float ov = __shfl_down_sync(0xffffffffu, x, o);
            int   oi = __shfl_down_sync(0xffffffffu, idx, o);
            if (ov > x || (ov == x && oi < idx)) { x = ov; idx = oi; }
        }
        if (lane == 0) { s_cv[j][wid] = x; s_ci[j][wid] = idx; }
    }
    __syncthreads();
    if (t == 0) {
        float cv[8]; int ci[8];
        for (int c = 0; c < 8; c++) {
            float bvv = NEG_INF; int bii = 0x7fffffff;
            for (int w2 = 0; w2 < 16; w2++) {
                float x = s_cv[c][w2]; int idx = s_ci[c][w2];
                if (x > bvv || (x == bvv && idx < bii)) { bvv = x; bii = idx; }
            }
            cv[c] = bvv; ci[c] = bii;
        }
        bool used[8] = {false,false,false,false,false,false,false,false};
        for (int k = 0; k < PKK; k++) {
            int bc = -1; float bvv = NEG_INF;
            for (int c = 0; c < 8; c++)
                if (!used[c] && cv[c] > bvv) { bvv = cv[c]; bc = c; }
            used[bc] = true;
            chos[k] = ci[bc];
        }
    }
    __syncthreads();
    int c0 = chos[0], c1 = chos[1], c2 = chos[2];

    // ---- exclusion mask for chosen proxies ----
    unsigned long long ex = 0ull;
#pragma unroll
    for (int k = 0; k < 3; k++) {
        int ck = (k == 0) ? c0 : (k == 1 ? c1 : c2);
        if (((ck >> 3) & 511) == t) {
            int slot = ((ck >> 3) >> 9) * 8 + (ck & 7);
            ex |= (1ull << slot);
        }
    }

    // ---- masked max, bisection, gather, exact rank ----
    float m = NEG_INF;
#pragma unroll
    for (int s = 0; s < 64; s++) m = fmaxf(m, ((ex >> s) & 1ull) ? NEG_INF : v[s]);
    float Mx = blockMaxF(m, s16, t);

    unsigned klo = 0u, khi = fkey(Mx);
    int C = PN;
    for (int iter = 0; iter < 40; iter++) {
        if (C <= 400 || khi - klo <= 1u) break;
        unsigned mid = klo + ((khi - klo) >> 1);
        float pm = unfkey(mid);
        int c = 0;
#pragma unroll
        for (int s = 0; s < 64; s++)
            c += (!((ex >> s) & 1ull) && (v[s] > pm)) ? 1 : 0;
        int tot = blockSumI(c, si16, t);
        if (tot >= BGK) { klo = mid; C = tot; }
        else             khi = mid;
    }
    float pf = unfkey(klo);

    __syncthreads();
#pragma unroll
    for (int s = 0; s < 64; s++) {
        if (!((ex >> s) & 1ull) && (v[s] > pf)) {
            unsigned k = atomicAdd(&sh_cnt, 1u);
            if (k < 512u) {
                candv[k] = v[s];
                candi[k] = 8 * (t + 512 * (s >> 3)) + (s & 7);
            }
        }
    }
    if (t == 0) { fin[0] = c0; fin[1] = c1; fin[2] = c2; }
    __syncthreads();
    int nc = (int)min(sh_cnt, 512u);
    for (int i = t; i < nc; i += 512) {
        float x = candv[i]; int pi = candi[i];
        int r = 0;
        for (int j = 0; j < nc; j++) {
            float w = candv[j];
            r += (w > x) || (w == x && candi[j] < pi);
        }
        if (r < BGK) {
            unsigned k = atomicAdd(&sh_nf, 1u);
            if (k < 64u) fin[k] = pi;
        }
    }
    __syncthreads();
    int nf = (int)min(sh_nf, 64u);   // 53

    // ---- lse over INPUTS at the 53 indices ----
    float val = (t < nf) ? ri[fin[t]] : NEG_INF;
    float mo = blockMaxF(val, s16, t);
    float e  = (t < nf) ? __expf(val - mo) : 0.f;
    float se = blockSumF(e, red, t);   // separate buffer ok (16 floats used)
    if (t == 0) {
        float csum = ri[c0] + ri[c1] + ri[c2];
        g_loss[2 * BN + b] = mo + logf(se) - csum * (1.0f / 3.0f);
    }
}

// ---------------- K5: final reduction (coalesced) ----------------
__global__ void k_final(const int* __restrict__ cams, float* __restrict__ out) {
    __shared__ float sv[256];
    __shared__ int   sc[256];
    __shared__ float s8[8];
    int t = threadIdx.x;
    sv[t] = g_loss[t] + g_loss[BN + t] + g_loss[2 * BN + t];
    sc[t] = cams[t];
    __syncthreads();
    if (t < 8) {
        float acc = 0.f; int n = 0;
        for (int b = 0; b < BN; b++)
            if (sc[b] == t) { acc += sv[b]; n++; }
        s8[t] = (n > 0) ? acc / (float)n : 0.f;
    }
    __syncthreads();
    if (t == 0) {
        float tot = 0.f;
        for (int c = 0; c < 8; c++) tot += s8[c];
        out[0] = tot;
    }
}

// ---------------- launch ----------------
extern "C" void kernel_launch(void* const* d_in, const int* in_sizes, int n_in,
                              void* d_out, int out_size) {
    const float* features        = (const float*)d_in[0];
    const int*   targets         = (const int*)d_in[1];
    const int*   cams            = (const int*)d_in[2];
    const float* global_memory   = (const float*)d_in[4];
    const int*   all_proxy_label = (const int*)d_in[6];
    float* out = (float*)d_out;

    k_prep<<<BN, DN>>>(features, targets, all_proxy_label, global_memory);
    dim3 gg(PN / 128, BN / 64);
    k_gemm<<<gg, 256>>>(global_memory);
    k_lossA<<<BN, 512>>>(cams);
    k_lossB<<<BN, 512>>>();
    k_final<<<1, 256>>>(cams, out);
}

// round 5
// speedup vs baseline: 1.2080x; 1.2080x over previous
#include <cuda_runtime.h>
#include <math.h>
#include <stdint.h>

#define BN   256      // batch
#define PN   32768    // proxies
#define DN   256      // feature dim
#define CN   8        // cameras
#define KSCALE 20.0f  // 1/TEMP
#define BGK  50
#define PKK  3
#define BALW 0.15f
#define CAP  768      // candidate buffer size

#define NEG_INF (__int_as_float(0xff800000))

// ---------------- scratch ----------------
__device__ float g_A[2 * BN * DN];
__device__ int   g_pseudo[BN];
__device__ float g_inputs[(size_t)BN * PN];    // 32 MB
__device__ float g_sims[(size_t)BN * PN];      // 32 MB
__device__ float g_loss[3 * BN];

__device__ __forceinline__ unsigned fkey(float v) {
    unsigned u = __float_as_uint(v);
    return (u & 0x80000000u) ? ~u : (u | 0x80000000u);
}
__device__ __forceinline__ float unfkey(unsigned k) {
    unsigned u = (k & 0x80000000u) ? (k ^ 0x80000000u) : ~k;
    return __uint_as_float(u);
}

__device__ __forceinline__ float blockMaxF(float x, float* s16, int t) {
    int lane = t & 31, wid = t >> 5;
    for (int o = 16; o > 0; o >>= 1) x = fmaxf(x, __shfl_xor_sync(0xffffffffu, x, o));
    __syncthreads();
    if (lane == 0) s16[wid] = x;
    __syncthreads();
    if (t == 0) { float y = s16[0]; for (int w = 1; w < 16; w++) y = fmaxf(y, s16[w]); s16[0] = y; }
    __syncthreads();
    return s16[0];
}
__device__ __forceinline__ float blockSumF(float x, float* s16, int t) {
    int lane = t & 31, wid = t >> 5;
    for (int o = 16; o > 0; o >>= 1) x += __shfl_xor_sync(0xffffffffu, x, o);
    __syncthreads();
    if (lane == 0) s16[wid] = x;
    __syncthreads();
    if (t == 0) { float y = 0.f; for (int w = 0; w < 16; w++) y += s16[w]; s16[0] = y; }
    __syncthreads();
    return s16[0];
}
__device__ __forceinline__ int blockSumI(int x, int* s16, int t) {
    int lane = t & 31, wid = t >> 5;
    for (int o = 16; o > 0; o >>= 1) x += __shfl_xor_sync(0xffffffffu, x, o);
    __syncthreads();
    if (lane == 0) s16[wid] = x;
    __syncthreads();
    if (t == 0) { int y = 0; for (int w = 0; w < 16; w++) y += s16[w]; s16[0] = y; }
    __syncthreads();
    return s16[0];
}

// ---------------- K1: gather prx rows ----------------
__global__ void k_prep(const float* __restrict__ features,
                       const int* __restrict__ targets,
                       const int* __restrict__ all_proxy_label,
                       const float* __restrict__ mem) {
    int b = blockIdx.x;
    int t = threadIdx.x;
    int tgt = targets[b];
    int prx = all_proxy_label[tgt];
    if (t == 0) { g_pseudo[b] = prx / CN; }
    g_A[b * DN + t]        = features[b * DN + t];
    g_A[(BN + b) * DN + t] = mem[(size_t)prx * DN + t];
}

// ---------------- K2: fused dual GEMM (unchanged) ----------------
__global__ __launch_bounds__(256, 2) void k_gemm(const float* __restrict__ mem) {
    __shared__ float sAf[16][65];
    __shared__ float sAp[16][65];
    __shared__ float sB[16][132];

    const int t  = threadIdx.x;
    const int tx = t & 15;
    const int ty = t >> 4;
    const int p0 = blockIdx.x * 128;
    const int b0 = blockIdx.y * 64;

    float accF[4][8];
    float accP[4][8];
#pragma unroll
    for (int i = 0; i < 4; i++)
#pragma unroll
        for (int j = 0; j < 8; j++) { accF[i][j] = 0.f; accP[i][j] = 0.f; }

    const int ar  = t >> 2;
    const int akc = (t & 3) << 2;
    const float* gAf = g_A + (size_t)(b0 + ar) * DN + akc;
    const float* gAp = g_A + (size_t)(BN + b0 + ar) * DN + akc;

    for (int k0 = 0; k0 < DN; k0 += 16) {
        float4 va = *(const float4*)(gAf + k0);
        float4 vp = *(const float4*)(gAp + k0);
        sAf[akc + 0][ar] = va.x; sAf[akc + 1][ar] = va.y;
        sAf[akc + 2][ar] = va.z; sAf[akc + 3][ar] = va.w;
        sAp[akc + 0][ar] = vp.x; sAp[akc + 1][ar] = vp.y;
        sAp[akc + 2][ar] = vp.z; sAp[akc + 3][ar] = vp.w;
#pragma unroll
        for (int s = 0; s < 2; s++) {
            int idx = t + 256 * s;
            int r   = idx >> 2;
            int kc  = (idx & 3) << 2;
            float4 vb = *(const float4*)(mem + (size_t)(p0 + r) * DN + k0 + kc);
            sB[kc + 0][r] = vb.x; sB[kc + 1][r] = vb.y;
            sB[kc + 2][r] = vb.z; sB[kc + 3][r] = vb.w;
        }
        __syncthreads();
#pragma unroll
        for (int kk = 0; kk < 16; kk++) {
            float af[4], ap[4], bb[8];
#pragma unroll
            for (int i = 0; i < 4; i++) {
                af[i] = sAf[kk][ty * 4 + i];
                ap[i] = sAp[kk][ty * 4 + i];
            }
            float4 b0v = *(const float4*)&sB[kk][tx * 4];
            float4 b1v = *(const float4*)&sB[kk][64 + tx * 4];
            bb[0] = b0v.x; bb[1] = b0v.y; bb[2] = b0v.z; bb[3] = b0v.w;
            bb[4] = b1v.x; bb[5] = b1v.y; bb[6] = b1v.z; bb[7] = b1v.w;
#pragma unroll
            for (int i = 0; i < 4; i++)
#pragma unroll
                for (int j = 0; j < 8; j++) {
                    accF[i][j] = fmaf(af[i], bb[j], accF[i][j]);
                    accP[i][j] = fmaf(ap[i], bb[j], accP[i][j]);
                }
        }
        __syncthreads();
    }

#pragma unroll
    for (int i = 0; i < 4; i++) {
        int b = b0 + ty * 4 + i;
        float* rin = g_inputs + (size_t)b * PN + p0;
        float* rsm = g_sims   + (size_t)b * PN + p0;
        float4 o;
        o.x = KSCALE * accF[i][0]; o.y = KSCALE * accF[i][1];
        o.z = KSCALE * accF[i][2]; o.w = KSCALE * accF[i][3];
        *(float4*)(rin + tx * 4) = o;
        o.x = KSCALE * accF[i][4]; o.y = KSCALE * accF[i][5];
        o.z = KSCALE * accF[i][6]; o.w = KSCALE * accF[i][7];
        *(float4*)(rin + 64 + tx * 4) = o;
        o.x = BALW * accF[i][0] + (1.0f - BALW) * accP[i][0];
        o.y = BALW * accF[i][1] + (1.0f - BALW) * accP[i][1];
        o.z = BALW * accF[i][2] + (1.0f - BALW) * accP[i][2];
        o.w = BALW * accF[i][3] + (1.0f - BALW) * accP[i][3];
        *(float4*)(rsm + tx * 4) = o;
        o.x = BALW * accF[i][4] + (1.0f - BALW) * accP[i][4];
        o.y = BALW * accF[i][5] + (1.0f - BALW) * accP[i][5];
        o.z = BALW * accF[i][6] + (1.0f - BALW) * accP[i][6];
        o.w = BALW * accF[i][7] + (1.0f - BALW) * accP[i][7];
        *(float4*)(rsm + 64 + tx * 4) = o;
    }
}

// warp0-only: exact 50th-largest of 512 shared values via key bisection.
__device__ __forceinline__ void warp0_pivot(const float* tmax, int t,
                                            unsigned* sh_pk, float* sh_gm) {
    if (t < 32) {
        float m16[16];
#pragma unroll
        for (int k = 0; k < 16; k++) m16[k] = tmax[t + 32 * k];
        float gm = m16[0];
#pragma unroll
        for (int k = 1; k < 16; k++) gm = fmaxf(gm, m16[k]);
        for (int o = 16; o > 0; o >>= 1) gm = fmaxf(gm, __shfl_xor_sync(0xffffffffu, gm, o));
        unsigned klo = 0u, khi = fkey(gm);
#pragma unroll 1
        for (int it = 0; it < 32; it++) {
            if (khi - klo <= 1u) break;
            unsigned mid = klo + ((khi - klo) >> 1);
            float pm = unfkey(mid);
            int c = 0;
#pragma unroll
            for (int k = 0; k < 16; k++) c += (m16[k] > pm);
            for (int o = 16; o > 0; o >>= 1) c += __shfl_xor_sync(0xffffffffu, c, o);
            if (c >= BGK) klo = mid; else khi = mid;
        }
        if (t == 0) { *sh_pk = klo; *sh_gm = gm; }
    }
    __syncthreads();
}

// ---------------- K3: intra + cross ----------------
__global__ __launch_bounds__(512) void k_lossA(const int* __restrict__ cams) {
    __shared__ float s16[16];
    __shared__ int   si16[16];
    __shared__ float tmax[512];
    __shared__ float candv[CAP];
    __shared__ float sposv[8];
    __shared__ unsigned sh_pk;
    __shared__ float sh_gm;
    __shared__ unsigned sh_cnt;

    const int b = blockIdx.x, t = threadIdx.x;
    const float* ri = g_inputs + (size_t)b * PN;
    const int pseudo = g_pseudo[b];
    const int cam = cams[b];

    if (t == 0) sh_cnt = 0;
    if (t < 8) sposv[t] = ri[pseudo * 8 + t];

    float v[64];
    float vcam[8];
#pragma unroll
    for (int i = 0; i < 8; i++) {
        int chunk = t + 512 * i;
        const float4* p4 = (const float4*)(ri + 8 * chunk);
        float4 a = p4[0], c = p4[1];
        float sel = (cam < 4) ? ((cam < 2) ? (cam == 0 ? a.x : a.y)
                                           : (cam == 2 ? a.z : a.w))
                              : ((cam < 6) ? (cam == 4 ? c.x : c.y)
                                           : (cam == 6 ? c.z : c.w));
        vcam[i] = sel;
        bool grp = (chunk == pseudo);
        float ninf = NEG_INF;
        v[i*8+0] = grp ? ninf : a.x; v[i*8+1] = grp ? ninf : a.y;
        v[i*8+2] = grp ? ninf : a.z; v[i*8+3] = grp ? ninf : a.w;
        v[i*8+4] = grp ? ninf : c.x; v[i*8+5] = grp ? ninf : c.y;
        v[i*8+6] = grp ? ninf : c.z; v[i*8+7] = grp ? ninf : c.w;
    }

    float m = v[0];
#pragma unroll
    for (int s = 1; s < 64; s++) m = fmaxf(m, v[s]);
    tmax[t] = m;
    float mi = vcam[0];
#pragma unroll
    for (int i = 1; i < 8; i++) mi = fmaxf(mi, vcam[i]);
    float Mi = blockMaxF(mi, s16, t);
    __syncthreads();

    warp0_pivot(tmax, t, &sh_pk, &sh_gm);
    unsigned pk = sh_pk;
    float Mex = sh_gm;
    float M = Mex;
#pragma unroll
    for (int k = 0; k < 8; k++) M = fmaxf(M, sposv[k]);

    float pf = unfkey(pk);
    {
        int c = 0;
#pragma unroll
        for (int s = 0; s < 64; s++) c += (v[s] > pf);
        int tot = blockSumI(c, si16, t);
        unsigned pkhi = fkey(Mex);
#pragma unroll 1
        while (tot > CAP && pkhi - pk > 1u) {
            unsigned mid = pk + ((pkhi - pk) >> 1);
            float pm = unfkey(mid);
            int c2 = 0;
#pragma unroll
            for (int s = 0; s < 64; s++) c2 += (v[s] > pm);
            int t2 = blockSumI(c2, si16, t);
            if (t2 >= BGK) { pk = mid; tot = t2; }
            else pkhi = mid;
        }
        pf = unfkey(pk);
    }

#pragma unroll
    for (int s = 0; s < 64; s++) {
        if (v[s] > pf) {
            unsigned k = atomicAdd(&sh_cnt, 1u);
            if (k < (unsigned)CAP) candv[k] = v[s];
        }
    }
    __syncthreads();
    int nc = (int)min(sh_cnt, (unsigned)CAP);

    float seC = 0.f;
    for (int i = t; i < nc; i += 512) {
        float x = candv[i];
        int r = 0;
        for (int j = 0; j < nc; j++) {
            float w = candv[j];
            r += (w > x) || (w == x && j < i);
        }
        if (r < BGK) seC += __expf(x - M);
    }
    if (t < 8) seC += __expf(sposv[t] - M);
    float sumC = blockSumF(seC, s16, t);

    float seI = 0.f;
#pragma unroll
    for (int i = 0; i < 8; i++) seI += __expf(vcam[i] - Mi);
    float sumI = blockSumF(seI, s16, t);

    if (t == 0) {
        float psum = 0.f;
        for (int k = 0; k < 8; k++) psum += sposv[k];
        g_loss[b]      = Mi + logf(sumI) - sposv[cam];
        g_loss[BN + b] = M  + logf(sumC) - psum * 0.125f;
    }
}

// ---------------- K4: online ----------------
__global__ __launch_bounds__(512) void k_lossB() {
    __shared__ float s16[16];
    __shared__ int   si16[16];
    __shared__ float tmax[512];
    __shared__ float candv[CAP];
    __shared__ int   candi[CAP];
    __shared__ float s_cv[8][16];
    __shared__ int   s_ci[8][16];
    __shared__ int   chos[3];
    __shared__ int   fin[64];
    __shared__ unsigned sh_pk;
    __shared__ float sh_gm;
    __shared__ unsigned sh_cnt, sh_nf;

    const int b = blockIdx.x, t = threadIdx.x;
    const int lane = t & 31, wid = t >> 5;
    const float* rs = g_sims   + (size_t)b * PN;
    const float* ri = g_inputs + (size_t)b * PN;

    if (t == 0) { sh_cnt = 0; sh_nf = 3; }

    float v[64];
    float bv[8]; int bi[8];
#pragma unroll
    for (int j = 0; j < 8; j++) { bv[j] = NEG_INF; bi[j] = 0x7fffffff; }
#pragma unroll
    for (int i = 0; i < 8; i++) {
        int chunk = t + 512 * i;
        const float4* p4 = (const float4*)(rs + 8 * chunk);
        float4 a = p4[0], c = p4[1];
        v[i*8+0]=a.x; v[i*8+1]=a.y; v[i*8+2]=a.z; v[i*8+3]=a.w;
        v[i*8+4]=c.x; v[i*8+5]=c.y; v[i*8+6]=c.z; v[i*8+7]=c.w;
#pragma unroll
        for (int j = 0; j < 8; j++) {
            float x = v[i*8+j];
            if (x > bv[j]) { bv[j] = x; bi[j] = 8 * chunk + j; }
        }
    }

#pragma unroll
    for (int j = 0; j < 8; j++) {
        float x = bv[j]; int idx = bi[j];
        for (int o = 16; o > 0; o >>= 1) {
            float ov = __shfl_down_sync(0xffffffffu, x, o);
            int   oi = __shfl_down_sync(0xffffffffu, idx, o);
            if (ov > x || (ov == x && oi < idx)) { x = ov; idx = oi; }
        }
        if (lane == 0) { s_cv[j][wid] = x; s_ci[j][wid] = idx; }
    }
    __syncthreads();
    if (t == 0) {
        float cv[8]; int ci[8];
        for (int c = 0; c < 8; c++) {
            float bvv = NEG_INF; int bii = 0x7fffffff;
            for (int w2 = 0; w2 < 16; w2++) {
                float x = s_cv[c][w2]; int idx = s_ci[c][w2];
                if (x > bvv || (x == bvv && idx < bii)) { bvv = x; bii = idx; }
            }
            cv[c] = bvv; ci[c] = bii;
        }
        bool used[8] = {false,false,false,false,false,false,false,false};
        for (int k = 0; k < PKK; k++) {
            int bc = -1; float bvv = NEG_INF;
            for (int c = 0; c < 8; c++)
                if (!used[c] && cv[c] > bvv) { bvv = cv[c]; bc = c; }
            used[bc] = true;
            chos[k] = ci[bc];
        }
        fin[0] = chos[0]; fin[1] = chos[1]; fin[2] = chos[2];
    }
    __syncthreads();
    int c0 = chos[0], c1 = chos[1], c2 = chos[2];

#pragma unroll 1
    for (int k = 0; k < 3; k++) {
        int ck = (k == 0) ? c0 : (k == 1 ? c1 : c2);
        if (((ck >> 3) & 511) == t) {
            int slot = ((ck >> 3) >> 9) * 8 + (ck & 7);
#pragma unroll
            for (int s = 0; s < 64; s++)
                if (s == slot) v[s] = NEG_INF;
        }
    }

    float m = v[0];
#pragma unroll
    for (int s = 1; s < 64; s++) m = fmaxf(m, v[s]);
    tmax[t] = m;
    __syncthreads();
    warp0_pivot(tmax, t, &sh_pk, &sh_gm);
    unsigned pk = sh_pk;
    float pf = unfkey(pk);
    {
        int c = 0;
#pragma unroll
        for (int s = 0; s < 64; s++) c += (v[s] > pf);
        int tot = blockSumI(c, si16, t);
        unsigned pkhi = fkey(sh_gm);
#pragma unroll 1
        while (tot > CAP && pkhi - pk > 1u) {
            unsigned mid = pk + ((pkhi - pk) >> 1);
            float pm = unfkey(mid);
            int c2 = 0;
#pragma unroll
            for (int s = 0; s < 64; s++) c2 += (v[s] > pm);
            int t2 = blockSumI(c2, si16, t);
            if (t2 >= BGK) { pk = mid; tot = t2; }
            else pkhi = mid;
        }
        pf = unfkey(pk);
    }
#pragma unroll
    for (int s = 0; s < 64; s++) {
        if (v[s] > pf) {
            unsigned k = atomicAdd(&sh_cnt, 1u);
            if (k < (unsigned)CAP) {
                candv[k] = v[s];
                candi[k] = 8 * (t + 512 * (s >> 3)) + (s & 7);
            }
        }
    }
    __syncthreads();
    int nc = (int)min(sh_cnt, (unsigned)CAP);

    for (int i = t; i < nc; i += 512) {
        float x = candv[i]; int pi = candi[i];
        int r = 0;
        for (int j = 0; j < nc; j++) {
            float w = candv[j];
            r += (w > x) || (w == x && candi[j] < pi);
        }
        if (r < BGK) {
            unsigned k = atomicAdd(&sh_nf, 1u);
            if (k < 64u) fin[k] = pi;
        }
    }
    __syncthreads();
    int nf = (int)min(sh_nf, 64u);   // 53

    float val = (t < nf) ? ri[fin[t]] : NEG_INF;
    float mo = blockMaxF(val, s16, t);
    float e  = (t < nf) ? __expf(val - mo) : 0.f;
    float se = blockSumF(e, s16, t);
    if (t == 0) {
        float csum = ri[c0] + ri[c1] + ri[c2];
        g_loss[2 * BN + b] = mo + logf(se) - csum * (1.0f / 3.0f);
    }
}

// ---------------- K5: final reduction ----------------
__global__ void k_final(const int* __restrict__ cams, float* __restrict__ out) {
    __shared__ float sv[256];
    __shared__ int   sc[256];
    __shared__ float s8[8];
    int t = threadIdx.x;
    sv[t] = g_loss[t] + g_loss[BN + t] + g_loss[2 * BN + t];
    sc[t] = cams[t];
    __syncthreads();
    if (t < 8) {
        float acc = 0.f; int n = 0;
        for (int b = 0; b < BN; b++)
            if (sc[b] == t) { acc += sv[b]; n++; }
        s8[t] = (n > 0) ? acc / (float)n : 0.f;
    }
    __syncthreads();
    if (t == 0) {
        float tot = 0.f;
        for (int c = 0; c < 8; c++) tot += s8[c];
        out[0] = tot;
    }
}

// ---------------- launch ----------------
extern "C" void kernel_launch(void* const* d_in, const int* in_sizes, int n_in,
                              void* d_out, int out_size) {
    const float* features        = (const float*)d_in[0];
    const int*   targets         = (const int*)d_in[1];
    const int*   cams            = (const int*)d_in[2];
    const float* global_memory   = (const float*)d_in[4];
    const int*   all_proxy_label = (const int*)d_in[6];
    float* out = (float*)d_out;

    k_prep<<<BN, DN>>>(features, targets, all_proxy_label, global_memory);
    dim3 gg(PN / 128, BN / 64);
    k_gemm<<<gg, 256>>>(global_memory);
    k_lossA<<<BN, 512>>>(cams);
    k_lossB<<<BN, 512>>>();
    k_final<<<1, 256>>>(cams, out);
}

// round 7
// speedup vs baseline: 1.9217x; 1.5908x over previous
#include <cuda_runtime.h>
#include <cuda_bf16.h>
#include <math.h>
#include <stdint.h>

#define BN   256      // batch
#define PN   32768    // proxies
#define DN   256      // feature dim
#define CN   8        // cameras
#define KSCALE 20.0f  // 1/TEMP
#define BGK  50
#define PKK  3
#define BALW 0.15f
#define CAP  768

#define NEG_INF (__int_as_float(0xff800000))

// ---------------- scratch ----------------
__device__ int   g_pseudo[BN];
__device__ __nv_bfloat16 g_Ahi[2 * BN * DN];   // rows 0..255 features, 256..511 mem[prx]
__device__ __nv_bfloat16 g_Alo[2 * BN * DN];
__device__ __nv_bfloat16 g_Bhi[(size_t)PN * DN];
__device__ __nv_bfloat16 g_Blo[(size_t)PN * DN];
__device__ float g_score[(size_t)BN * PN];     // raw features@mem^T
__device__ float g_psim [(size_t)BN * PN];     // raw mem[prx]@mem^T
__device__ float g_loss[3 * BN];

// ---------------- PTX helpers (sm_80-era, valid on plain sm_100) -----------
__device__ __forceinline__ uint32_t smem_u32(const void* p) {
    uint32_t a;
    asm("{ .reg .u64 t; cvta.to.shared.u64 t, %1; cvt.u32.u64 %0, t; }" : "=r"(a) : "l"(p));
    return a;
}
#define SW128(off) ((off) ^ (((off) >> 3) & 0x70))
__device__ __forceinline__ void cp16(uint32_t dst, const void* src) {
    asm volatile("cp.async.cg.shared.global [%0], [%1], 16;" :: "r"(dst), "l"(src));
}
__device__ __forceinline__ void cp_commit() { asm volatile("cp.async.commit_group;"); }
template <int N>
__device__ __forceinline__ void cp_wait() { asm volatile("cp.async.wait_group %0;" :: "n"(N)); }

__device__ __forceinline__ void ldsm_x4(uint32_t addr, uint32_t& r0, uint32_t& r1,
                                        uint32_t& r2, uint32_t& r3) {
    asm volatile("ldmatrix.sync.aligned.m8n8.x4.shared.b16 {%0,%1,%2,%3}, [%4];"
        : "=r"(r0), "=r"(r1), "=r"(r2), "=r"(r3) : "r"(addr));
}
__device__ __forceinline__ void mma_bf16(float& c0, float& c1, float& c2, float& c3,
                                         uint32_t a0, uint32_t a1, uint32_t a2, uint32_t a3,
                                         uint32_t b0, uint32_t b1) {
    asm volatile("mma.sync.aligned.m16n8k16.row.col.f32.bf16.bf16.f32 "
        "{%0,%1,%2,%3}, {%4,%5,%6,%7}, {%8,%9}, {%0,%1,%2,%3};"
        : "+f"(c0), "+f"(c1), "+f"(c2), "+f"(c3)
        : "r"(a0), "r"(a1), "r"(a2), "r"(a3), "r"(b0), "r"(b1));
}

// ---------------- selection helpers ----------------
__device__ __forceinline__ unsigned fkey(float v) {
    unsigned u = __float_as_uint(v);
    return (u & 0x80000000u) ? ~u : (u | 0x80000000u);
}
__device__ __forceinline__ float unfkey(unsigned k) {
    unsigned u = (k & 0x80000000u) ? (k ^ 0x80000000u) : ~k;
    return __uint_as_float(u);
}
__device__ __forceinline__ float blockMaxF(float x, float* s16, int t) {
    int lane = t & 31, wid = t >> 5;
    for (int o = 16; o > 0; o >>= 1) x = fmaxf(x, __shfl_xor_sync(0xffffffffu, x, o));
    __syncthreads();
    if (lane == 0) s16[wid] = x;
    __syncthreads();
    if (t == 0) { float y = s16[0]; for (int w = 1; w < 16; w++) y = fmaxf(y, s16[w]); s16[0] = y; }
    __syncthreads();
    return s16[0];
}
__device__ __forceinline__ float blockSumF(float x, float* s16, int t) {
    int lane = t & 31, wid = t >> 5;
    for (int o = 16; o > 0; o >>= 1) x += __shfl_xor_sync(0xffffffffu, x, o);
    __syncthreads();
    if (lane == 0) s16[wid] = x;
    __syncthreads();
    if (t == 0) { float y = 0.f; for (int w = 0; w < 16; w++) y += s16[w]; s16[0] = y; }
    __syncthreads();
    return s16[0];
}
__device__ __forceinline__ int blockSumI(int x, int* s16, int t) {
    int lane = t & 31, wid = t >> 5;
    for (int o = 16; o > 0; o >>= 1) x += __shfl_xor_sync(0xffffffffu, x, o);
    __syncthreads();
    if (lane == 0) s16[wid] = x;
    __syncthreads();
    if (t == 0) { int y = 0; for (int w = 0; w < 16; w++) y += s16[w]; s16[0] = y; }
    __syncthreads();
    return s16[0];
}

// ---------------- K1: gather + A hi/lo conversion ----------------
__global__ void k_prep(const float* __restrict__ features,
                       const int* __restrict__ targets,
                       const int* __restrict__ all_proxy_label,
                       const float* __restrict__ mem) {
    int b = blockIdx.x;
    int t = threadIdx.x;
    int tgt = targets[b];
    int prx = all_proxy_label[tgt];
    if (t == 0) g_pseudo[b] = prx / CN;
    float f = features[b * DN + t];
    __nv_bfloat16 fh = __float2bfloat16_rn(f);
    g_Ahi[b * DN + t] = fh;
    g_Alo[b * DN + t] = __float2bfloat16_rn(f - __bfloat162float(fh));
    float m = mem[(size_t)prx * DN + t];
    __nv_bfloat16 mh = __float2bfloat16_rn(m);
    g_Ahi[(BN + b) * DN + t] = mh;
    g_Alo[(BN + b) * DN + t] = __float2bfloat16_rn(m - __bfloat162float(mh));
}

// ---------------- K1b: B hi/lo conversion ----------------
__global__ __launch_bounds__(256) void k_conv(const float* __restrict__ mem) {
    int t = threadIdx.x;
    size_t base = (size_t)blockIdx.x * 8192;
#pragma unroll
    for (int i = 0; i < 8; i++) {
        size_t off = base + (size_t)i * 1024 + t * 4;
        float4 f = *(const float4*)(mem + off);
        __nv_bfloat162 h01 = __floats2bfloat162_rn(f.x, f.y);
        __nv_bfloat162 h23 = __floats2bfloat162_rn(f.z, f.w);
        float lx = f.x - __bfloat162float(__low2bfloat16(h01));
        float ly = f.y - __bfloat162float(__high2bfloat16(h01));
        float lz = f.z - __bfloat162float(__low2bfloat16(h23));
        float lw = f.w - __bfloat162float(__high2bfloat16(h23));
        __nv_bfloat162 l01 = __floats2bfloat162_rn(lx, ly);
        __nv_bfloat162 l23 = __floats2bfloat162_rn(lz, lw);
        ((__nv_bfloat162*)(g_Bhi + off))[0] = h01;
        ((__nv_bfloat162*)(g_Bhi + off))[1] = h23;
        ((__nv_bfloat162*)(g_Blo + off))[0] = l01;
        ((__nv_bfloat162*)(g_Blo + off))[1] = l23;
    }
}

// ---------------- K2: mma.sync bf16 3-term GEMM ----------------
// grid (PN/128 = 256 ntiles, 4 mtiles), 256 threads, warp grid 2(M)x4(N),
// warp tile 64x32, K = 256 in 4 chunks of 64, 2-stage cp.async pipeline.
#define KCH 64
#define STAGE_STRIDE 65536   // 4 x 16KB (Ahi, Alo, Bhi, Blo)
#define SMEM_GEMM (2 * STAGE_STRIDE)

__global__ __launch_bounds__(256, 1) void k_gemm_mma() {
    extern __shared__ char smem[];
    const uint32_t sb = smem_u32(smem);
    const int t = threadIdx.x;
    const int lane = t & 31, w = t >> 5;
    const int warp_m = w >> 2, warp_n = w & 3;
    const int n0 = blockIdx.x * 128;
    const int m0g = blockIdx.y * 128;

    float acc[4][4][4];
#pragma unroll
    for (int i = 0; i < 4; i++)
#pragma unroll
        for (int j = 0; j < 4; j++)
#pragma unroll
            for (int q = 0; q < 4; q++) acc[i][j][q] = 0.f;

    // precomputed cp.async (row, kc) per j
    const int cprow = t >> 3;     // uses idx = t + 256j -> row = cprow + 32j
    const int cpkc  = t & 7;

#define ISSUE(c, s)                                                                    \
    {                                                                                  \
        int k0 = (c) * KCH;                                                            \
        uint32_t st = sb + (s) * STAGE_STRIDE;                                         \
        _Pragma("unroll")                                                              \
        for (int j = 0; j < 4; j++) {                                                  \
            int row = cprow + 32 * j;                                                  \
            uint32_t d = SW128((uint32_t)(row * 128 + cpkc * 16));                     \
            const __nv_bfloat16* ah = g_Ahi + (size_t)(m0g + row) * DN + k0 + cpkc * 8;\
            const __nv_bfloat16* al = g_Alo + (size_t)(m0g + row) * DN + k0 + cpkc * 8;\
            const __nv_bfloat16* bh = g_Bhi + (size_t)(n0 + row) * DN + k0 + cpkc * 8; \
            const __nv_bfloat16* bl = g_Blo + (size_t)(n0 + row) * DN + k0 + cpkc * 8; \
            cp16(st + d, ah);                                                          \
            cp16(st + 16384 + d, al);                                                  \
            cp16(st + 32768 + d, bh);                                                  \
            cp16(st + 49152 + d, bl);                                                  \
        }                                                                              \
        cp_commit();                                                                   \
    }

#define COMPUTE(s)                                                                     \
    {                                                                                  \
        uint32_t stAh = sb + (s) * STAGE_STRIDE;                                       \
        uint32_t stAl = stAh + 16384;                                                  \
        uint32_t stBh = stAh + 32768;                                                  \
        uint32_t stBl = stAh + 49152;                                                  \
        const int arow = warp_m * 64 + (lane & 15);                                    \
        const int acolb = (lane >> 4) << 4;                                            \
        const int brow = warp_n * 32 + (lane & 7) + ((lane >> 4) << 3);                \
        const int bcolb = ((lane >> 3) & 1) << 4;                                      \
        _Pragma("unroll")                                                              \
        for (int ks = 0; ks < 4; ks++) {                                               \
            uint32_t ah[4][4], al[4][4];                                               \
            _Pragma("unroll")                                                          \
            for (int mf = 0; mf < 4; mf++) {                                           \
                uint32_t off = SW128((uint32_t)((arow + mf * 16) * 128 + ks * 32 + acolb)); \
                ldsm_x4(stAh + off, ah[mf][0], ah[mf][1], ah[mf][2], ah[mf][3]);       \
                ldsm_x4(stAl + off, al[mf][0], al[mf][1], al[mf][2], al[mf][3]);       \
            }                                                                          \
            uint32_t bh[4][2], bl[4][2];                                               \
            _Pragma("unroll")                                                          \
            for (int h = 0; h < 2; h++) {                                              \
                uint32_t off = SW128((uint32_t)((brow + h * 16) * 128 + ks * 32 + bcolb)); \
                uint32_t r0, r1, r2, r3;                                               \
                ldsm_x4(stBh + off, r0, r1, r2, r3);                                   \
                bh[h*2][0] = r0; bh[h*2][1] = r1; bh[h*2+1][0] = r2; bh[h*2+1][1] = r3;\
                ldsm_x4(stBl + off, r0, r1, r2, r3);                                   \
                bl[h*2][0] = r0; bl[h*2][1] = r1; bl[h*2+1][0] = r2; bl[h*2+1][1] = r3;\
            }                                                                          \
            _Pragma("unroll")                                                          \
            for (int mf = 0; mf < 4; mf++)                                             \
                _Pragma("unroll")                                                      \
                for (int nf = 0; nf < 4; nf++) {                                       \
                    mma_bf16(acc[mf][nf][0], acc[mf][nf][1], acc[mf][nf][2], acc[mf][nf][3], \
                             ah[mf][0], ah[mf][1], ah[mf][2], ah[mf][3], bh[nf][0], bh[nf][1]); \
                    mma_bf16(acc[mf][nf][0], acc[mf][nf][1], acc[mf][nf][2], acc[mf][nf][3], \
                             ah[mf][0], ah[mf][1], ah[mf][2], ah[mf][3], bl[nf][0], bl[nf][1]); \
                    mma_bf16(acc[mf][nf][0], acc[mf][nf][1], acc[mf][nf][2], acc[mf][nf][3], \
                             al[mf][0], al[mf][1], al[mf][2], al[mf][3], bh[nf][0], bh[nf][1]); \
                }                                                                      \
        }                                                                              \
    }

    ISSUE(0, 0);
    ISSUE(1, 1);

    cp_wait<1>(); __syncthreads();
    COMPUTE(0);  __syncthreads();
    ISSUE(2, 0);

    cp_wait<1>(); __syncthreads();
    COMPUTE(1);  __syncthreads();
    ISSUE(3, 1);

    cp_wait<1>(); __syncthreads();
    COMPUTE(0);  __syncthreads();

    cp_wait<0>(); __syncthreads();
    COMPUTE(1);

    // ---- epilogue: direct fragment stores ----
    const int gr = lane >> 2;
    const int gc = (lane & 3) * 2;
#pragma unroll
    for (int mf = 0; mf < 4; mf++) {
#pragma unroll
        for (int nf = 0; nf < 4; nf++) {
            int row0 = m0g + warp_m * 64 + mf * 16 + gr;
            int col  = n0 + warp_n * 32 + nf * 8 + gc;
            float* outp = (row0 < 256) ? g_score : g_psim;
            int r0 = row0 & 255;
            float2 v0 = make_float2(acc[mf][nf][0], acc[mf][nf][1]);
            float2 v1 = make_float2(acc[mf][nf][2], acc[mf][nf][3]);
            *(float2*)(outp + (size_t)r0 * PN + col)       = v0;
            *(float2*)(outp + (size_t)(r0 + 8) * PN + col) = v1;
        }
    }
}

// warp0-only: exact 50th-largest of 512 shared values via key bisection.
__device__ __forceinline__ void warp0_pivot(const float* tmax, int t,
                                            unsigned* sh_pk, float* sh_gm) {
    if (t < 32) {
        float m16[16];
#pragma unroll
        for (int k = 0; k < 16; k++) m16[k] = tmax[t + 32 * k];
        float gm = m16[0];
#pragma unroll
        for (int k = 1; k < 16; k++) gm = fmaxf(gm, m16[k]);
        for (int o = 16; o > 0; o >>= 1) gm = fmaxf(gm, __shfl_xor_sync(0xffffffffu, gm, o));
        unsigned klo = 0u, khi = fkey(gm);
#pragma unroll 1
        for (int it = 0; it < 32; it++) {
            if (khi - klo <= 1u) break;
            unsigned mid = klo + ((khi - klo) >> 1);
            float pm = unfkey(mid);
            int c = 0;
#pragma unroll
            for (int k = 0; k < 16; k++) c += (m16[k] > pm);
            for (int o = 16; o > 0; o >>= 1) c += __shfl_xor_sync(0xffffffffu, c, o);
            if (c >= BGK) klo = mid; else khi = mid;
        }
        if (t == 0) { *sh_pk = klo; *sh_gm = gm; }
    }
    __syncthreads();
}

// ---------------- K3: intra + cross (reads g_score, scales x20) ----------------
__global__ __launch_bounds__(512) void k_lossA(const int* __restrict__ cams) {
    __shared__ float s16[16];
    __shared__ int   si16[16];
    __shared__ float tmax[512];
    __shared__ float candv[CAP];
    __shared__ float sposv[8];
    __shared__ unsigned sh_pk;
    __shared__ float sh_gm;
    __shared__ unsigned sh_cnt;

    const int b = blockIdx.x, t = threadIdx.x;
    const float* ri = g_score + (size_t)b * PN;
    const int pseudo = g_pseudo[b];
    const int cam = cams[b];

    if (t == 0) sh_cnt = 0;
    if (t < 8) sposv[t] = KSCALE * ri[pseudo * 8 + t];

    float v[64];
    float vcam[8];
#pragma unroll
    for (int i = 0; i < 8; i++) {
        int chunk = t + 512 * i;
        const float4* p4 = (const float4*)(ri + 8 * chunk);
        float4 a = p4[0], c = p4[1];
        a.x *= KSCALE; a.y *= KSCALE; a.z *= KSCALE; a.w *= KSCALE;
        c.x *= KSCALE; c.y *= KSCALE; c.z *= KSCALE; c.w *= KSCALE;
        float sel = (cam < 4) ? ((cam < 2) ? (cam == 0 ? a.x : a.y)
                                           : (cam == 2 ? a.z : a.w))
                              : ((cam < 6) ? (cam == 4 ? c.x : c.y)
                                           : (cam == 6 ? c.z : c.w));
        vcam[i] = sel;
        bool grp = (chunk == pseudo);
        float ninf = NEG_INF;
        v[i*8+0] = grp ? ninf : a.x; v[i*8+1] = grp ? ninf : a.y;
        v[i*8+2] = grp ? ninf : a.z; v[i*8+3] = grp ? ninf : a.w;
        v[i*8+4] = grp ? ninf : c.x; v[i*8+5] = grp ? ninf : c.y;
        v[i*8+6] = grp ? ninf : c.z; v[i*8+7] = grp ? ninf : c.w;
    }

    float m = v[0];
#pragma unroll
    for (int s = 1; s < 64; s++) m = fmaxf(m, v[s]);
    tmax[t] = m;
    float mi = vcam[0];
#pragma unroll
    for (int i = 1; i < 8; i++) mi = fmaxf(mi, vcam[i]);
    float Mi = blockMaxF(mi, s16, t);
    __syncthreads();

    warp0_pivot(tmax, t, &sh_pk, &sh_gm);
    unsigned pk = sh_pk;
    float Mex = sh_gm;
    float M = Mex;
#pragma unroll
    for (int k = 0; k < 8; k++) M = fmaxf(M, sposv[k]);

    float pf = unfkey(pk);
    {
        int c = 0;
#pragma unroll
        for (int s = 0; s < 64; s++) c += (v[s] > pf);
        int tot = blockSumI(c, si16, t);
        unsigned pkhi = fkey(Mex);
#pragma unroll 1
        while (tot > CAP && pkhi - pk > 1u) {
            unsigned mid = pk + ((pkhi - pk) >> 1);
            float pm = unfkey(mid);
            int c2 = 0;
#pragma unroll
            for (int s = 0; s < 64; s++) c2 += (v[s] > pm);
            int t2 = blockSumI(c2, si16, t);
            if (t2 >= BGK) { pk = mid; tot = t2; }
            else pkhi = mid;
        }
        pf = unfkey(pk);
    }

#pragma unroll
    for (int s = 0; s < 64; s++) {
        if (v[s] > pf) {
            unsigned k = atomicAdd(&sh_cnt, 1u);
            if (k < (unsigned)CAP) candv[k] = v[s];
        }
    }
    __syncthreads();
    int nc = (int)min(sh_cnt, (unsigned)CAP);

    float seC = 0.f;
    for (int i = t; i < nc; i += 512) {
        float x = candv[i];
        int r = 0;
        for (int j = 0; j < nc; j++) {
            float w = candv[j];
            r += (w > x) || (w == x && j < i);
        }
        if (r < BGK) seC += __expf(x - M);
    }
    if (t < 8) seC += __expf(sposv[t] - M);
    float sumC = blockSumF(seC, s16, t);

    float seI = 0.f;
#pragma unroll
    for (int i = 0; i < 8; i++) seI += __expf(vcam[i] - Mi);
    float sumI = blockSumF(seI, s16, t);

    if (t == 0) {
        float psum = 0.f;
        for (int k = 0; k < 8; k++) psum += sposv[k];
        g_loss[b]      = Mi + logf(sumI) - sposv[cam];
        g_loss[BN + b] = M  + logf(sumC) - psum * 0.125f;
    }
}

// ---------------- K4: online (sims built from score+psim on the fly) ----------
__global__ __launch_bounds__(512) void k_lossB() {
    __shared__ float s16[16];
    __shared__ int   si16[16];
    __shared__ float tmax[512];
    __shared__ float candv[CAP];
    __shared__ int   candi[CAP];
    __shared__ float s_cv[8][16];
    __shared__ int   s_ci[8][16];
    __shared__ int   chos[3];
    __shared__ int   fin[64];
    __shared__ unsigned sh_pk;
    __shared__ float sh_gm;
    __shared__ unsigned sh_cnt, sh_nf;

    const int b = blockIdx.x, t = threadIdx.x;
    const int lane = t & 31, wid = t >> 5;
    const float* rsc = g_score + (size_t)b * PN;
    const float* rps = g_psim  + (size_t)b * PN;

    if (t == 0) { sh_cnt = 0; sh_nf = 3; }

    float v[64];
    float bv[8]; int bi[8];
#pragma unroll
    for (int j = 0; j < 8; j++) { bv[j] = NEG_INF; bi[j] = 0x7fffffff; }
#pragma unroll
    for (int i = 0; i < 8; i++) {
        int chunk = t + 512 * i;
        const float4* s4 = (const float4*)(rsc + 8 * chunk);
        const float4* p4 = (const float4*)(rps + 8 * chunk);
        float4 sa = s4[0], sc = s4[1];
        float4 pa = p4[0], pc = p4[1];
        v[i*8+0] = BALW * sa.x + (1.0f - BALW) * pa.x;
        v[i*8+1] = BALW * sa.y + (1.0f - BALW) * pa.y;
        v[i*8+2] = BALW * sa.z + (1.0f - BALW) * pa.z;
        v[i*8+3] = BALW * sa.w + (1.0f - BALW) * pa.w;
        v[i*8+4] = BALW * sc.x + (1.0f - BALW) * pc.x;
        v[i*8+5] = BALW * sc.y + (1.0f - BALW) * pc.y;
        v[i*8+6] = BALW * sc.z + (1.0f - BALW) * pc.z;
        v[i*8+7] = BALW * sc.w + (1.0f - BALW) * pc.w;
#pragma unroll
        for (int j = 0; j < 8; j++) {
            float x = v[i*8+j];
            if (x > bv[j]) { bv[j] = x; bi[j] = 8 * chunk + j; }
        }
    }

#pragma unroll
    for (int j = 0; j < 8; j++) {
        float x = bv[j]; int idx = bi[j];
        for (int o = 16; o > 0; o >>= 1) {
            float ov = __shfl_down_sync(0xffffffffu, x, o);
            int   oi = __shfl_down_sync(0xffffffffu, idx, o);
            if (ov > x || (ov == x && oi < idx)) { x = ov; idx = oi; }
        }
        if (lane == 0) { s_cv[j][wid] = x; s_ci[j][wid] = idx; }
    }
    __syncthreads();
    if (t == 0) {
        float cv[8]; int ci[8];
        for (int c = 0; c < 8; c++) {
            float bvv = NEG_INF; int bii = 0x7fffffff;
            for (int w2 = 0; w2 < 16; w2++) {
                float x = s_cv[c][w2]; int idx = s_ci[c][w2];
                if (x > bvv || (x == bvv && idx < bii)) { bvv = x; bii = idx; }
            }
            cv[c] = bvv; ci[c] = bii;
        }
        bool used[8] = {false,false,false,false,false,false,false,false};
        for (int k = 0; k < PKK; k++) {
            int bc = -1; float bvv = NEG_INF;
            for (int c = 0; c < 8; c++)
                if (!used[c] && cv[c] > bvv) { bvv = cv[c]; bc = c; }
            used[bc] = true;
            chos[k] = ci[bc];
        }
        fin[0] = chos[0]; fin[1] = chos[1]; fin[2] = chos[2];
    }
    __syncthreads();
    int c0 = chos[0], c1 = chos[1], c2 = chos[2];

#pragma unroll 1
    for (int k = 0; k < 3; k++) {
        int ck = (k == 0) ? c0 : (k == 1 ? c1 : c2);
        if (((ck >> 3) & 511) == t) {
            int slot = ((ck >> 3) >> 9) * 8 + (ck & 7);
#pragma unroll
            for (int s = 0; s < 64; s++)
                if (s == slot) v[s] = NEG_INF;
        }
    }

    float m = v[0];
#pragma unroll
    for (int s = 1; s < 64; s++) m = fmaxf(m, v[s]);
    tmax[t] = m;
    __syncthreads();
    warp0_pivot(tmax, t, &sh_pk, &sh_gm);
    unsigned pk = sh_pk;
    float pf = unfkey(pk);
    {
        int c = 0;
#pragma unroll
        for (int s = 0; s < 64; s++) c += (v[s] > pf);
        int tot = blockSumI(c, si16, t);
        unsigned pkhi = fkey(sh_gm);
#pragma unroll 1
        while (tot > CAP && pkhi - pk > 1u) {
            unsigned mid = pk + ((pkhi - pk) >> 1);
            float pm = unfkey(mid);
            int c2 = 0;
#pragma unroll
            for (int s = 0; s < 64; s++) c2 += (v[s] > pm);
            int t2 = blockSumI(c2, si16, t);
            if (t2 >= BGK) { pk = mid; tot = t2; }
            else pkhi = mid;
        }
        pf = unfkey(pk);
    }
#pragma unroll
    for (int s = 0; s < 64; s++) {
        if (v[s] > pf) {
            unsigned k = atomicAdd(&sh_cnt, 1u);
            if (k < (unsigned)CAP) {
                candv[k] = v[s];
                candi[k] = 8 * (t + 512 * (s >> 3)) + (s & 7);
            }
        }
    }
    __syncthreads();
    int nc = (int)min(sh_cnt, (unsigned)CAP);

    for (int i = t; i < nc; i += 512) {
        float x = candv[i]; int pi = candi[i];
        int r = 0;
        for (int j = 0; j < nc; j++) {
            float w = candv[j];
            r += (w > x) || (w == x && candi[j] < pi);
        }
        if (r < BGK) {
            unsigned k = atomicAdd(&sh_nf, 1u);
            if (k < 64u) fin[k] = pi;
        }
    }
    __syncthreads();
    int nf = (int)min(sh_nf, 64u);   // 53

    float val = (t < nf) ? KSCALE * rsc[fin[t]] : NEG_INF;
    float mo = blockMaxF(val, s16, t);
    float e  = (t < nf) ? __expf(val - mo) : 0.f;
    float se = blockSumF(e, s16, t);
    if (t == 0) {
        float csum = KSCALE * rsc[c0] + KSCALE * rsc[c1] + KSCALE * rsc[c2];
        g_loss[2 * BN + b] = mo + logf(se) - csum * (1.0f / 3.0f);
    }
}

// ---------------- K5: final reduction ----------------
__global__ void k_final(const int* __restrict__ cams, float* __restrict__ out) {
    __shared__ float sv[256];
    __shared__ int   sc[256];
    __shared__ float s8[8];
    int t = threadIdx.x;
    sv[t] = g_loss[t] + g_loss[BN + t] + g_loss[2 * BN + t];
    sc[t] = cams[t];
    __syncthreads();
    if (t < 8) {
        float acc = 0.f; int n = 0;
        for (int b = 0; b < BN; b++)
            if (sc[b] == t) { acc += sv[b]; n++; }
        s8[t] = (n > 0) ? acc / (float)n : 0.f;
    }
    __syncthreads();
    if (t == 0) {
        float tot = 0.f;
        for (int c = 0; c < 8; c++) tot += s8[c];
        out[0] = tot;
    }
}

// ---------------- launch ----------------
extern "C" void kernel_launch(void* const* d_in, const int* in_sizes, int n_in,
                              void* d_out, int out_size) {
    const float* features        = (const float*)d_in[0];
    const int*   targets         = (const int*)d_in[1];
    const int*   cams            = (const int*)d_in[2];
    const float* global_memory   = (const float*)d_in[4];
    const int*   all_proxy_label = (const int*)d_in[6];
    float* out = (float*)d_out;

    cudaFuncSetAttribute(k_gemm_mma, cudaFuncAttributeMaxDynamicSharedMemorySize, SMEM_GEMM);

    k_prep<<<BN, DN>>>(features, targets, all_proxy_label, global_memory);
    k_conv<<<(PN * DN) / 8192, 256>>>(global_memory);
    dim3 gg(PN / 128, 4);
    k_gemm_mma<<<gg, 256, SMEM_GEMM>>>();
    k_lossA<<<BN, 512>>>(cams);
    k_lossB<<<BN, 512>>>();
    k_final<<<1, 256>>>(cams, out);
}

// round 8
// speedup vs baseline: 1.9661x; 1.0231x over previous
#include <cuda_runtime.h>
#include <cuda_bf16.h>
#include <math.h>
#include <stdint.h>

#define BN   256      // batch
#define PN   32768    // proxies
#define DN   256      // feature dim
#define CN   8        // cameras
#define KSCALE 20.0f  // 1/TEMP
#define BGK  50
#define PKK  3
#define BALW 0.15f
#define CAP  768

#define NEG_INF (__int_as_float(0xff800000))

// ---------------- scratch ----------------
__device__ int   g_pseudo[BN];
__device__ __nv_bfloat16 g_Ahi[2 * BN * DN];   // rows 0..255 features, 256..511 blended (0.15f+0.85m)
__device__ __nv_bfloat16 g_Alo[2 * BN * DN];
__device__ __nv_bfloat16 g_Bhi[(size_t)PN * DN];
__device__ __nv_bfloat16 g_Blo[(size_t)PN * DN];
__device__ float g_score[(size_t)BN * PN];     // raw features@mem^T
__device__ float g_sims [(size_t)BN * PN];     // blended@mem^T  == 0.15*score + 0.85*psim
__device__ float g_loss[3 * BN];

// ---------------- PTX helpers (sm_80-era, valid on plain sm_100) -----------
__device__ __forceinline__ uint32_t smem_u32(const void* p) {
    uint32_t a;
    asm("{ .reg .u64 t; cvta.to.shared.u64 t, %1; cvt.u32.u64 %0, t; }" : "=r"(a) : "l"(p));
    return a;
}
#define SW128(off) ((off) ^ (((off) >> 3) & 0x70))
__device__ __forceinline__ void cp16(uint32_t dst, const void* src) {
    asm volatile("cp.async.cg.shared.global [%0], [%1], 16;" :: "r"(dst), "l"(src));
}
__device__ __forceinline__ void cp_commit() { asm volatile("cp.async.commit_group;"); }
template <int N>
__device__ __forceinline__ void cp_wait() { asm volatile("cp.async.wait_group %0;" :: "n"(N)); }

__device__ __forceinline__ void ldsm_x4(uint32_t addr, uint32_t& r0, uint32_t& r1,
                                        uint32_t& r2, uint32_t& r3) {
    asm volatile("ldmatrix.sync.aligned.m8n8.x4.shared.b16 {%0,%1,%2,%3}, [%4];"
        : "=r"(r0), "=r"(r1), "=r"(r2), "=r"(r3) : "r"(addr));
}
__device__ __forceinline__ void mma_bf16(float& c0, float& c1, float& c2, float& c3,
                                         uint32_t a0, uint32_t a1, uint32_t a2, uint32_t a3,
                                         uint32_t b0, uint32_t b1) {
    asm volatile("mma.sync.aligned.m16n8k16.row.col.f32.bf16.bf16.f32 "
        "{%0,%1,%2,%3}, {%4,%5,%6,%7}, {%8,%9}, {%0,%1,%2,%3};"
        : "+f"(c0), "+f"(c1), "+f"(c2), "+f"(c3)
        : "r"(a0), "r"(a1), "r"(a2), "r"(a3), "r"(b0), "r"(b1));
}

// ---------------- selection helpers ----------------
__device__ __forceinline__ unsigned fkey(float v) {
    unsigned u = __float_as_uint(v);
    return (u & 0x80000000u) ? ~u : (u | 0x80000000u);
}
__device__ __forceinline__ float unfkey(unsigned k) {
    unsigned u = (k & 0x80000000u) ? (k ^ 0x80000000u) : ~k;
    return __uint_as_float(u);
}
__device__ __forceinline__ float blockMaxF(float x, float* s16, int t) {
    int lane = t & 31, wid = t >> 5;
    for (int o = 16; o > 0; o >>= 1) x = fmaxf(x, __shfl_xor_sync(0xffffffffu, x, o));
    __syncthreads();
    if (lane == 0) s16[wid] = x;
    __syncthreads();
    if (t == 0) { float y = s16[0]; for (int w = 1; w < 16; w++) y = fmaxf(y, s16[w]); s16[0] = y; }
    __syncthreads();
    return s16[0];
}
__device__ __forceinline__ float blockSumF(float x, float* s16, int t) {
    int lane = t & 31, wid = t >> 5;
    for (int o = 16; o > 0; o >>= 1) x += __shfl_xor_sync(0xffffffffu, x, o);
    __syncthreads();
    if (lane == 0) s16[wid] = x;
    __syncthreads();
    if (t == 0) { float y = 0.f; for (int w = 0; w < 16; w++) y += s16[w]; s16[0] = y; }
    __syncthreads();
    return s16[0];
}
__device__ __forceinline__ int blockSumI(int x, int* s16, int t) {
    int lane = t & 31, wid = t >> 5;
    for (int o = 16; o > 0; o >>= 1) x += __shfl_xor_sync(0xffffffffu, x, o);
    __syncthreads();
    if (lane == 0) s16[wid] = x;
    __syncthreads();
    if (t == 0) { int y = 0; for (int w = 0; w < 16; w++) y += s16[w]; s16[0] = y; }
    __syncthreads();
    return s16[0];
}

// ---------------- K1: gather + blended A + hi/lo conversion ----------------
__global__ void k_prep(const float* __restrict__ features,
                       const int* __restrict__ targets,
                       const int* __restrict__ all_proxy_label,
                       const float* __restrict__ mem) {
    int b = blockIdx.x;
    int t = threadIdx.x;
    int tgt = targets[b];
    int prx = all_proxy_label[tgt];
    if (t == 0) g_pseudo[b] = prx / CN;
    float f = features[b * DN + t];
    __nv_bfloat16 fh = __float2bfloat16_rn(f);
    g_Ahi[b * DN + t] = fh;
    g_Alo[b * DN + t] = __float2bfloat16_rn(f - __bfloat162float(fh));
    float m = mem[(size_t)prx * DN + t];
    float bl = BALW * f + (1.0f - BALW) * m;
    __nv_bfloat16 bh = __float2bfloat16_rn(bl);
    g_Ahi[(BN + b) * DN + t] = bh;
    g_Alo[(BN + b) * DN + t] = __float2bfloat16_rn(bl - __bfloat162float(bh));
}

// ---------------- K1b: B hi/lo conversion ----------------
__global__ __launch_bounds__(256) void k_conv(const float* __restrict__ mem) {
    int t = threadIdx.x;
    size_t base = (size_t)blockIdx.x * 8192;
#pragma unroll
    for (int i = 0; i < 8; i++) {
        size_t off = base + (size_t)i * 1024 + t * 4;
        float4 f = *(const float4*)(mem + off);
        __nv_bfloat162 h01 = __floats2bfloat162_rn(f.x, f.y);
        __nv_bfloat162 h23 = __floats2bfloat162_rn(f.z, f.w);
        float lx = f.x - __bfloat162float(__low2bfloat16(h01));
        float ly = f.y - __bfloat162float(__high2bfloat16(h01));
        float lz = f.z - __bfloat162float(__low2bfloat16(h23));
        float lw = f.w - __bfloat162float(__high2bfloat16(h23));
        __nv_bfloat162 l01 = __floats2bfloat162_rn(lx, ly);
        __nv_bfloat162 l23 = __floats2bfloat162_rn(lz, lw);
        ((__nv_bfloat162*)(g_Bhi + off))[0] = h01;
        ((__nv_bfloat162*)(g_Bhi + off))[1] = h23;
        ((__nv_bfloat162*)(g_Blo + off))[0] = l01;
        ((__nv_bfloat162*)(g_Blo + off))[1] = l23;
    }
}

// ---------------- K2: mma.sync bf16 3-term GEMM, 2 M-blocks per CTA ---------
// grid (PN/128 = 256 ntiles, 2 mtiles), 256 threads, warp grid 2(M)x4(N),
// warp tile 64x32, K = 256 in 4 chunks of 64, 2-stage cp.async pipeline.
// Each CTA computes score rows [m0,+128) and sims rows [m0,+128) reusing B tiles.
#define KCH 64
#define STAGE_STRIDE 98304   // 6 x 16KB (Ahi_s, Alo_s, Ahi_b, Alo_b, Bhi, Blo)
#define SMEM_GEMM (2 * STAGE_STRIDE)

__global__ __launch_bounds__(256, 1) void k_gemm_mma() {
    extern __shared__ char smem[];
    const uint32_t sb = smem_u32(smem);
    const int t = threadIdx.x;
    const int lane = t & 31, w = t >> 5;
    const int warp_m = w >> 2, warp_n = w & 3;
    const int n0 = blockIdx.x * 128;
    const int m0 = blockIdx.y * 128;       // batch-row block (0 or 128)

    float acc[2][4][4][4];
#pragma unroll
    for (int z = 0; z < 2; z++)
#pragma unroll
        for (int i = 0; i < 4; i++)
#pragma unroll
            for (int j = 0; j < 4; j++)
#pragma unroll
                for (int q = 0; q < 4; q++) acc[z][i][j][q] = 0.f;

    const int cprow = t >> 3;
    const int cpkc  = t & 7;

#define ISSUE(c, s)                                                                    \
    {                                                                                  \
        int k0 = (c) * KCH;                                                            \
        uint32_t st = sb + (s) * STAGE_STRIDE;                                         \
        _Pragma("unroll")                                                              \
        for (int j = 0; j < 4; j++) {                                                  \
            int row = cprow + 32 * j;                                                  \
            uint32_t d = SW128((uint32_t)(row * 128 + cpkc * 16));                     \
            const __nv_bfloat16* ahs = g_Ahi + (size_t)(m0 + row) * DN + k0 + cpkc * 8;       \
            const __nv_bfloat16* als = g_Alo + (size_t)(m0 + row) * DN + k0 + cpkc * 8;       \
            const __nv_bfloat16* ahb = g_Ahi + (size_t)(BN + m0 + row) * DN + k0 + cpkc * 8;  \
            const __nv_bfloat16* alb = g_Alo + (size_t)(BN + m0 + row) * DN + k0 + cpkc * 8;  \
            const __nv_bfloat16* bh  = g_Bhi + (size_t)(n0 + row) * DN + k0 + cpkc * 8;       \
            const __nv_bfloat16* bl  = g_Blo + (size_t)(n0 + row) * DN + k0 + cpkc * 8;       \
            cp16(st + d, ahs);                                                         \
            cp16(st + 16384 + d, als);                                                 \
            cp16(st + 32768 + d, ahb);                                                 \
            cp16(st + 49152 + d, alb);                                                 \
            cp16(st + 65536 + d, bh);                                                  \
            cp16(st + 81920 + d, bl);                                                  \
        }                                                                              \
        cp_commit();                                                                   \
    }

#define COMPUTE(s)                                                                     \
    {                                                                                  \
        uint32_t st = sb + (s) * STAGE_STRIDE;                                         \
        uint32_t stBh = st + 65536;                                                    \
        uint32_t stBl = st + 81920;                                                    \
        const int arow = warp_m * 64 + (lane & 15);                                    \
        const int acolb = (lane >> 4) << 4;                                            \
        const int brow = warp_n * 32 + (lane & 7) + ((lane >> 4) << 3);                \
        const int bcolb = ((lane >> 3) & 1) << 4;                                      \
        _Pragma("unroll")                                                              \
        for (int ks = 0; ks < 4; ks++) {                                               \
            uint32_t bh[4][2], bl[4][2];                                               \
            _Pragma("unroll")                                                          \
            for (int h = 0; h < 2; h++) {                                              \
                uint32_t off = SW128((uint32_t)((brow + h * 16) * 128 + ks * 32 + bcolb)); \
                uint32_t r0, r1, r2, r3;                                               \
                ldsm_x4(stBh + off, r0, r1, r2, r3);                                   \
                bh[h*2][0] = r0; bh[h*2][1] = r1; bh[h*2+1][0] = r2; bh[h*2+1][1] = r3;\
                ldsm_x4(stBl + off, r0, r1, r2, r3);                                   \
                bl[h*2][0] = r0; bl[h*2][1] = r1; bl[h*2+1][0] = r2; bl[h*2+1][1] = r3;\
            }                                                                          \
            _Pragma("unroll")                                                          \
            for (int z = 0; z < 2; z++) {                                              \
                uint32_t stAh = st + z * 32768;                                        \
                uint32_t stAl = stAh + 16384;                                          \
                _Pragma("unroll")                                                      \
                for (int mf = 0; mf < 4; mf++) {                                       \
                    uint32_t ah0, ah1, ah2, ah3, al0, al1, al2, al3;                   \
                    uint32_t off = SW128((uint32_t)((arow + mf * 16) * 128 + ks * 32 + acolb)); \
                    ldsm_x4(stAh + off, ah0, ah1, ah2, ah3);                           \
                    ldsm_x4(stAl + off, al0, al1, al2, al3);                           \
                    _Pragma("unroll")                                                  \
                    for (int nf = 0; nf < 4; nf++) {                                   \
                        mma_bf16(acc[z][mf][nf][0], acc[z][mf][nf][1], acc[z][mf][nf][2], acc[z][mf][nf][3], \
                                 ah0, ah1, ah2, ah3, bh[nf][0], bh[nf][1]);            \
                        mma_bf16(acc[z][mf][nf][0], acc[z][mf][nf][1], acc[z][mf][nf][2], acc[z][mf][nf][3], \
                                 ah0, ah1, ah2, ah3, bl[nf][0], bl[nf][1]);            \
                        mma_bf16(acc[z][mf][nf][0], acc[z][mf][nf][1], acc[z][mf][nf][2], acc[z][mf][nf][3], \
                                 al0, al1, al2, al3, bh[nf][0], bh[nf][1]);            \
                    }                                                                  \
                }                                                                      \
            }                                                                          \
        }                                                                              \
    }

    ISSUE(0, 0);
    ISSUE(1, 1);

    cp_wait<1>(); __syncthreads();
    COMPUTE(0);  __syncthreads();
    ISSUE(2, 0);

    cp_wait<1>(); __syncthreads();
    COMPUTE(1);  __syncthreads();
    ISSUE(3, 1);

    cp_wait<1>(); __syncthreads();
    COMPUTE(0);  __syncthreads();

    cp_wait<0>(); __syncthreads();
    COMPUTE(1);

    // ---- epilogue: direct fragment stores ----
    const int gr = lane >> 2;
    const int gc = (lane & 3) * 2;
#pragma unroll
    for (int z = 0; z < 2; z++) {
        float* outp = (z == 0) ? g_score : g_sims;
#pragma unroll
        for (int mf = 0; mf < 4; mf++) {
#pragma unroll
            for (int nf = 0; nf < 4; nf++) {
                int r0 = m0 + warp_m * 64 + mf * 16 + gr;
                int col = n0 + warp_n * 32 + nf * 8 + gc;
                float2 v0 = make_float2(acc[z][mf][nf][0], acc[z][mf][nf][1]);
                float2 v1 = make_float2(acc[z][mf][nf][2], acc[z][mf][nf][3]);
                *(float2*)(outp + (size_t)r0 * PN + col)       = v0;
                *(float2*)(outp + (size_t)(r0 + 8) * PN + col) = v1;
            }
        }
    }
}

// warp0-only: exact 50th-largest of 512 shared values via key bisection.
__device__ __forceinline__ void warp0_pivot(const float* tmax, int t,
                                            unsigned* sh_pk, float* sh_gm) {
    if (t < 32) {
        float m16[16];
#pragma unroll
        for (int k = 0; k < 16; k++) m16[k] = tmax[t + 32 * k];
        float gm = m16[0];
#pragma unroll
        for (int k = 1; k < 16; k++) gm = fmaxf(gm, m16[k]);
        for (int o = 16; o > 0; o >>= 1) gm = fmaxf(gm, __shfl_xor_sync(0xffffffffu, gm, o));
        unsigned klo = 0u, khi = fkey(gm);
#pragma unroll 1
        for (int it = 0; it < 32; it++) {
            if (khi - klo <= 1u) break;
            unsigned mid = klo + ((khi - klo) >> 1);
            float pm = unfkey(mid);
            int c = 0;
#pragma unroll
            for (int k = 0; k < 16; k++) c += (m16[k] > pm);
            for (int o = 16; o > 0; o >>= 1) c += __shfl_xor_sync(0xffffffffu, c, o);
            if (c >= BGK) klo = mid; else khi = mid;
        }
        if (t == 0) { *sh_pk = klo; *sh_gm = gm; }
    }
    __syncthreads();
}

// ---------------- K3: intra + cross (reads g_score, scales x20) ----------------
__global__ __launch_bounds__(512) void k_lossA(const int* __restrict__ cams) {
    __shared__ float s16[16];
    __shared__ int   si16[16];
    __shared__ float tmax[512];
    __shared__ float candv[CAP];
    __shared__ float sposv[8];
    __shared__ unsigned sh_pk;
    __shared__ float sh_gm;
    __shared__ unsigned sh_cnt;

    const int b = blockIdx.x, t = threadIdx.x;
    const float* ri = g_score + (size_t)b * PN;
    const int pseudo = g_pseudo[b];
    const int cam = cams[b];

    if (t == 0) sh_cnt = 0;
    if (t < 8) sposv[t] = KSCALE * ri[pseudo * 8 + t];

    float v[64];
    float vcam[8];
#pragma unroll
    for (int i = 0; i < 8; i++) {
        int chunk = t + 512 * i;
        const float4* p4 = (const float4*)(ri + 8 * chunk);
        float4 a = p4[0], c = p4[1];
        a.x *= KSCALE; a.y *= KSCALE; a.z *= KSCALE; a.w *= KSCALE;
        c.x *= KSCALE; c.y *= KSCALE; c.z *= KSCALE; c.w *= KSCALE;
        float sel = (cam < 4) ? ((cam < 2) ? (cam == 0 ? a.x : a.y)
                                           : (cam == 2 ? a.z : a.w))
                              : ((cam < 6) ? (cam == 4 ? c.x : c.y)
                                           : (cam == 6 ? c.z : c.w));
        vcam[i] = sel;
        bool grp = (chunk == pseudo);
        float ninf = NEG_INF;
        v[i*8+0] = grp ? ninf : a.x; v[i*8+1] = grp ? ninf : a.y;
        v[i*8+2] = grp ? ninf : a.z; v[i*8+3] = grp ? ninf : a.w;
        v[i*8+4] = grp ? ninf : c.x; v[i*8+5] = grp ? ninf : c.y;
        v[i*8+6] = grp ? ninf : c.z; v[i*8+7] = grp ? ninf : c.w;
    }

    float m = v[0];
#pragma unroll
    for (int s = 1; s < 64; s++) m = fmaxf(m, v[s]);
    tmax[t] = m;
    float mi = vcam[0];
#pragma unroll
    for (int i = 1; i < 8; i++) mi = fmaxf(mi, vcam[i]);
    float Mi = blockMaxF(mi, s16, t);
    __syncthreads();

    warp0_pivot(tmax, t, &sh_pk, &sh_gm);
    unsigned pk = sh_pk;
    float Mex = sh_gm;
    float M = Mex;
#pragma unroll
    for (int k = 0; k < 8; k++) M = fmaxf(M, sposv[k]);

    float pf = unfkey(pk);
    {
        int c = 0;
#pragma unroll
        for (int s = 0; s < 64; s++) c += (v[s] > pf);
        int tot = blockSumI(c, si16, t);
        unsigned pkhi = fkey(Mex);
#pragma unroll 1
        while (tot > CAP && pkhi - pk > 1u) {
            unsigned mid = pk + ((pkhi - pk) >> 1);
            float pm = unfkey(mid);
            int c2 = 0;
#pragma unroll
            for (int s = 0; s < 64; s++) c2 += (v[s] > pm);
            int t2 = blockSumI(c2, si16, t);
            if (t2 >= BGK) { pk = mid; tot = t2; }
            else pkhi = mid;
        }
        pf = unfkey(pk);
    }

#pragma unroll
    for (int s = 0; s < 64; s++) {
        if (v[s] > pf) {
            unsigned k = atomicAdd(&sh_cnt, 1u);
            if (k < (unsigned)CAP) candv[k] = v[s];
        }
    }
    __syncthreads();
    int nc = (int)min(sh_cnt, (unsigned)CAP);

    float seC = 0.f;
    for (int i = t; i < nc; i += 512) {
        float x = candv[i];
        int r = 0;
        for (int j = 0; j < nc; j++) {
            float w = candv[j];
            r += (w > x) || (w == x && j < i);
        }
        if (r < BGK) seC += __expf(x - M);
    }
    if (t < 8) seC += __expf(sposv[t] - M);
    float sumC = blockSumF(seC, s16, t);

    float seI = 0.f;
#pragma unroll
    for (int i = 0; i < 8; i++) seI += __expf(vcam[i] - Mi);
    float sumI = blockSumF(seI, s16, t);

    if (t == 0) {
        float psum = 0.f;
        for (int k = 0; k < 8; k++) psum += sposv[k];
        g_loss[b]      = Mi + logf(sumI) - sposv[cam];
        g_loss[BN + b] = M  + logf(sumC) - psum * 0.125f;
    }
}

// ---------------- K4: online (reads g_sims directly) ----------
__global__ __launch_bounds__(512) void k_lossB() {
    __shared__ float s16[16];
    __shared__ int   si16[16];
    __shared__ float tmax[512];
    __shared__ float candv[CAP];
    __shared__ int   candi[CAP];
    __shared__ float s_cv[8][16];
    __shared__ int   s_ci[8][16];
    __shared__ int   chos[3];
    __shared__ int   fin[64];
    __shared__ unsigned sh_pk;
    __shared__ float sh_gm;
    __shared__ unsigned sh_cnt, sh_nf;

    const int b = blockIdx.x, t = threadIdx.x;
    const int lane = t & 31, wid = t >> 5;
    const float* rsm = g_sims  + (size_t)b * PN;
    const float* rsc = g_score + (size_t)b * PN;

    if (t == 0) { sh_cnt = 0; sh_nf = 3; }

    float v[64];
    float bv[8]; int bi[8];
#pragma unroll
    for (int j = 0; j < 8; j++) { bv[j] = NEG_INF; bi[j] = 0x7fffffff; }
#pragma unroll
    for (int i = 0; i < 8; i++) {
        int chunk = t + 512 * i;
        const float4* p4 = (const float4*)(rsm + 8 * chunk);
        float4 a = p4[0], c = p4[1];
        v[i*8+0]=a.x; v[i*8+1]=a.y; v[i*8+2]=a.z; v[i*8+3]=a.w;
        v[i*8+4]=c.x; v[i*8+5]=c.y; v[i*8+6]=c.z; v[i*8+7]=c.w;
#pragma unroll
        for (int j = 0; j < 8; j++) {
            float x = v[i*8+j];
            if (x > bv[j]) { bv[j] = x; bi[j] = 8 * chunk + j; }
        }
    }

#pragma unroll
    for (int j = 0; j < 8; j++) {
        float x = bv[j]; int idx = bi[j];
        for (int o = 16; o > 0; o >>= 1) {
            float ov = __shfl_down_sync(0xffffffffu, x, o);
            int   oi = __shfl_down_sync(0xffffffffu, idx, o);
            if (ov > x || (ov == x && oi < idx)) { x = ov; idx = oi; }
        }
        if (lane == 0) { s_cv[j][wid] = x; s_ci[j][wid] = idx; }
    }
    __syncthreads();
    if (t == 0) {
        float cv[8]; int ci[8];
        for (int c = 0; c < 8; c++) {
            float bvv = NEG_INF; int bii = 0x7fffffff;
            for (int w2 = 0; w2 < 16; w2++) {
                float x = s_cv[c][w2]; int idx = s_ci[c][w2];
                if (x > bvv || (x == bvv && idx < bii)) { bvv = x; bii = idx; }
            }
            cv[c] = bvv; ci[c] = bii;
        }
        bool used[8] = {false,false,false,false,false,false,false,false};
        for (int k = 0; k < PKK; k++) {
            int bc = -1; float bvv = NEG_INF;
            for (int c = 0; c < 8; c++)
                if (!used[c] && cv[c] > bvv) { bvv = cv[c]; bc = c; }
            used[bc] = true;
            chos[k] = ci[bc];
        }
        fin[0] = chos[0]; fin[1] = chos[1]; fin[2] = chos[2];
    }
    __syncthreads();
    int c0 = chos[0], c1 = chos[1], c2 = chos[2];

#pragma unroll 1
    for (int k = 0; k < 3; k++) {
        int ck = (k == 0) ? c0 : (k == 1 ? c1 : c2);
        if (((ck >> 3) & 511) == t) {
            int slot = ((ck >> 3) >> 9) * 8 + (ck & 7);
#pragma unroll
            for (int s = 0; s < 64; s++)
                if (s == slot) v[s] = NEG_INF;
        }
    }

    float m = v[0];
#pragma unroll
    for (int s = 1; s < 64; s++) m = fmaxf(m, v[s]);
    tmax[t] = m;
    __syncthreads();
    warp0_pivot(tmax, t, &sh_pk, &sh_gm);
    unsigned pk = sh_pk;
    float pf = unfkey(pk);
    {
        int c = 0;
#pragma unroll
        for (int s = 0; s < 64; s++) c += (v[s] > pf);
        int tot = blockSumI(c, si16, t);
        unsigned pkhi = fkey(sh_gm);
#pragma unroll 1
        while (tot > CAP && pkhi - pk > 1u) {
            unsigned mid = pk + ((pkhi - pk) >> 1);
            float pm = unfkey(mid);
            int c2 = 0;
#pragma unroll
            for (int s = 0; s < 64; s++) c2 += (v[s] > pm);
            int t2 = blockSumI(c2, si16, t);
            if (t2 >= BGK) { pk = mid; tot = t2; }
            else pkhi = mid;
        }
        pf = unfkey(pk);
    }
#pragma unroll
    for (int s = 0; s < 64; s++) {
        if (v[s] > pf) {
            unsigned k = atomicAdd(&sh_cnt, 1u);
            if (k < (unsigned)CAP) {
                candv[k] = v[s];
                candi[k] = 8 * (t + 512 * (s >> 3)) + (s & 7);
            }
        }
    }
    __syncthreads();
    int nc = (int)min(sh_cnt, (unsigned)CAP);

    for (int i = t; i < nc; i += 512) {
        float x = candv[i]; int pi = candi[i];
        int r = 0;
        for (int j = 0; j < nc; j++) {
            float w = candv[j];
            r += (w > x) || (w == x && candi[j] < pi);
        }
        if (r < BGK) {
            unsigned k = atomicAdd(&sh_nf, 1u);
            if (k < 64u) fin[k] = pi;
        }
    }
    __syncthreads();
    int nf = (int)min(sh_nf, 64u);   // 53

    float val = (t < nf) ? KSCALE * rsc[fin[t]] : NEG_INF;
    float mo = blockMaxF(val, s16, t);
    float e  = (t < nf) ? __expf(val - mo) : 0.f;
    float se = blockSumF(e, s16, t);
    if (t == 0) {
        float csum = KSCALE * rsc[c0] + KSCALE * rsc[c1] + KSCALE * rsc[c2];
        g_loss[2 * BN + b] = mo + logf(se) - csum * (1.0f / 3.0f);
    }
}

// ---------------- K5: final reduction ----------------
__global__ void k_final(const int* __restrict__ cams, float* __restrict__ out) {
    __shared__ float sv[256];
    __shared__ int   sc[256];
    __shared__ float s8[8];
    int t = threadIdx.x;
    sv[t] = g_loss[t] + g_loss[BN + t] + g_loss[2 * BN + t];
    sc[t] = cams[t];
    __syncthreads();
    if (t < 8) {
        float acc = 0.f; int n = 0;
        for (int b = 0; b < BN; b++)
            if (sc[b] == t) { acc += sv[b]; n++; }
        s8[t] = (n > 0) ? acc / (float)n : 0.f;
    }
    __syncthreads();
    if (t == 0) {
        float tot = 0.f;
        for (int c = 0; c < 8; c++) tot += s8[c];
        out[0] = tot;
    }
}

// ---------------- launch ----------------
extern "C" void kernel_launch(void* const* d_in, const int* in_sizes, int n_in,
                              void* d_out, int out_size) {
    const float* features        = (const float*)d_in[0];
    const int*   targets         = (const int*)d_in[1];
    const int*   cams            = (const int*)d_in[2];
    const float* global_memory   = (const float*)d_in[4];
    const int*   all_proxy_label = (const int*)d_in[6];
    float* out = (float*)d_out;

    cudaFuncSetAttribute(k_gemm_mma, cudaFuncAttributeMaxDynamicSharedMemorySize, SMEM_GEMM);

    k_prep<<<BN, DN>>>(features, targets, all_proxy_label, global_memory);
    k_conv<<<(PN * DN) / 8192, 256>>>(global_memory);
    dim3 gg(PN / 128, 2);
    k_gemm_mma<<<gg, 256, SMEM_GEMM>>>();
    k_lossA<<<BN, 512>>>(cams);
    k_lossB<<<BN, 512>>>();
    k_final<<<1, 256>>>(cams, out);
}

// round 9
// speedup vs baseline: 2.0186x; 1.0267x over previous
#include <cuda_runtime.h>
#include <cuda_bf16.h>
#include <math.h>
#include <stdint.h>

#define BN   256
#define PN   32768
#define DN   256
#define CN   8
#define KSCALE 20.0f
#define BGK  50
#define PKK  3
#define BALW 0.15f
#define CAP  768

#define NEG_INF (__int_as_float(0xff800000))

// ---------------- scratch ----------------
__device__ int   g_pseudo[BN];
__device__ __nv_bfloat16 g_Ahi[2 * BN * DN];   // rows 0..255 features, 256..511 blended
__device__ __nv_bfloat16 g_Alo[2 * BN * DN];
__device__ __nv_bfloat16 g_Bhi[(size_t)PN * DN];
__device__ __nv_bfloat16 g_Blo[(size_t)PN * DN];
__device__ float g_score[(size_t)BN * PN];
__device__ float g_sims [(size_t)BN * PN];
__device__ float g_loss[3 * BN];

// ---------------- PTX helpers ----------------
__device__ __forceinline__ uint32_t smem_u32(const void* p) {
    uint32_t a;
    asm("{ .reg .u64 t; cvta.to.shared.u64 t, %1; cvt.u32.u64 %0, t; }" : "=r"(a) : "l"(p));
    return a;
}
#define SW128(off) ((off) ^ (((off) >> 3) & 0x70))
__device__ __forceinline__ void cp16(uint32_t dst, const void* src) {
    asm volatile("cp.async.cg.shared.global [%0], [%1], 16;" :: "r"(dst), "l"(src));
}
__device__ __forceinline__ void cp_commit() { asm volatile("cp.async.commit_group;"); }
template <int N>
__device__ __forceinline__ void cp_wait() { asm volatile("cp.async.wait_group %0;" :: "n"(N)); }

__device__ __forceinline__ void ldsm_x4(uint32_t addr, uint32_t& r0, uint32_t& r1,
                                        uint32_t& r2, uint32_t& r3) {
    asm volatile("ldmatrix.sync.aligned.m8n8.x4.shared.b16 {%0,%1,%2,%3}, [%4];"
        : "=r"(r0), "=r"(r1), "=r"(r2), "=r"(r3) : "r"(addr));
}
__device__ __forceinline__ void mma_bf16(float& c0, float& c1, float& c2, float& c3,
                                         uint32_t a0, uint32_t a1, uint32_t a2, uint32_t a3,
                                         uint32_t b0, uint32_t b1) {
    asm volatile("mma.sync.aligned.m16n8k16.row.col.f32.bf16.bf16.f32 "
        "{%0,%1,%2,%3}, {%4,%5,%6,%7}, {%8,%9}, {%0,%1,%2,%3};"
        : "+f"(c0), "+f"(c1), "+f"(c2), "+f"(c3)
        : "r"(a0), "r"(a1), "r"(a2), "r"(a3), "r"(b0), "r"(b1));
}

// ---------------- selection helpers ----------------
__device__ __forceinline__ unsigned fkey(float v) {
    unsigned u = __float_as_uint(v);
    return (u & 0x80000000u) ? ~u : (u | 0x80000000u);
}
__device__ __forceinline__ float unfkey(unsigned k) {
    unsigned u = (k & 0x80000000u) ? (k ^ 0x80000000u) : ~k;
    return __uint_as_float(u);
}
__device__ __forceinline__ float blockMaxF(float x, float* s16, int t) {
    int lane = t & 31, wid = t >> 5;
    for (int o = 16; o > 0; o >>= 1) x = fmaxf(x, __shfl_xor_sync(0xffffffffu, x, o));
    __syncthreads();
    if (lane == 0) s16[wid] = x;
    __syncthreads();
    if (t == 0) { float y = s16[0]; for (int w = 1; w < 16; w++) y = fmaxf(y, s16[w]); s16[0] = y; }
    __syncthreads();
    return s16[0];
}
__device__ __forceinline__ float blockSumF(float x, float* s16, int t) {
    int lane = t & 31, wid = t >> 5;
    for (int o = 16; o > 0; o >>= 1) x += __shfl_xor_sync(0xffffffffu, x, o);
    __syncthreads();
    if (lane == 0) s16[wid] = x;
    __syncthreads();
    if (t == 0) { float y = 0.f; for (int w = 0; w < 16; w++) y += s16[w]; s16[0] = y; }
    __syncthreads();
    return s16[0];
}
__device__ __forceinline__ int blockSumI(int x, int* s16, int t) {
    int lane = t & 31, wid = t >> 5;
    for (int o = 16; o > 0; o >>= 1) x += __shfl_xor_sync(0xffffffffu, x, o);
    __syncthreads();
    if (lane == 0) s16[wid] = x;
    __syncthreads();
    if (t == 0) { int y = 0; for (int w = 0; w < 16; w++) y += s16[w]; s16[0] = y; }
    __syncthreads();
    return s16[0];
}

// ---------------- K1: merged prep (A blend + hi/lo) and B conversion -------
__global__ __launch_bounds__(256) void k_prep(const float* __restrict__ features,
                                              const int* __restrict__ targets,
                                              const int* __restrict__ all_proxy_label,
                                              const float* __restrict__ mem) {
    int blk = blockIdx.x;
    int t = threadIdx.x;
    if (blk < 1024) {
        // --- B hi/lo conversion ---
        size_t base = (size_t)blk * 8192;
#pragma unroll
        for (int i = 0; i < 8; i++) {
            size_t off = base + (size_t)i * 1024 + t * 4;
            float4 f = *(const float4*)(mem + off);
            __nv_bfloat162 h01 = __floats2bfloat162_rn(f.x, f.y);
            __nv_bfloat162 h23 = __floats2bfloat162_rn(f.z, f.w);
            float lx = f.x - __bfloat162float(__low2bfloat16(h01));
            float ly = f.y - __bfloat162float(__high2bfloat16(h01));
            float lz = f.z - __bfloat162float(__low2bfloat16(h23));
            float lw = f.w - __bfloat162float(__high2bfloat16(h23));
            __nv_bfloat162 l01 = __floats2bfloat162_rn(lx, ly);
            __nv_bfloat162 l23 = __floats2bfloat162_rn(lz, lw);
            ((__nv_bfloat162*)(g_Bhi + off))[0] = h01;
            ((__nv_bfloat162*)(g_Bhi + off))[1] = h23;
            ((__nv_bfloat162*)(g_Blo + off))[0] = l01;
            ((__nv_bfloat162*)(g_Blo + off))[1] = l23;
        }
    } else {
        // --- A gather + blend + hi/lo ---
        int b = blk - 1024;
        int tgt = targets[b];
        int prx = all_proxy_label[tgt];
        if (t == 0) g_pseudo[b] = prx / CN;
        float f = features[b * DN + t];
        __nv_bfloat16 fh = __float2bfloat16_rn(f);
        g_Ahi[b * DN + t] = fh;
        g_Alo[b * DN + t] = __float2bfloat16_rn(f - __bfloat162float(fh));
        float m = mem[(size_t)prx * DN + t];
        float bl = BALW * f + (1.0f - BALW) * m;
        __nv_bfloat16 bh = __float2bfloat16_rn(bl);
        g_Ahi[(BN + b) * DN + t] = bh;
        g_Alo[(BN + b) * DN + t] = __float2bfloat16_rn(bl - __bfloat162float(bh));
    }
}

// ---------------- K2: mma.sync bf16 3-term GEMM, 16 warps ------------------
// grid (256 ntiles, 2 mtiles), 512 threads, warp grid 4(M)x4(N),
// warp tile 32x32 per M-block (z), K = 256 in 4 chunks of 64, 2-stage pipeline.
#define KCH 64
#define STAGE_STRIDE 98304
#define SMEM_GEMM (2 * STAGE_STRIDE)

__global__ __launch_bounds__(512, 1) void k_gemm_mma() {
    extern __shared__ char smem[];
    const uint32_t sb = smem_u32(smem);
    const int t = threadIdx.x;
    const int lane = t & 31, w = t >> 5;
    const int warp_m = w >> 2, warp_n = w & 3;     // 4x4 warp grid
    const int n0 = blockIdx.x * 128;
    const int m0 = blockIdx.y * 128;

    float acc[2][2][4][4];
#pragma unroll
    for (int z = 0; z < 2; z++)
#pragma unroll
        for (int i = 0; i < 2; i++)
#pragma unroll
            for (int j = 0; j < 4; j++)
#pragma unroll
                for (int q = 0; q < 4; q++) acc[z][i][j][q] = 0.f;

    const int cprow = t >> 3;     // 0..63; row = cprow + 64*j
    const int cpkc  = t & 7;

#define ISSUE(c, s)                                                                    \
    {                                                                                  \
        int k0 = (c) * KCH;                                                            \
        uint32_t st = sb + (s) * STAGE_STRIDE;                                         \
        _Pragma("unroll")                                                              \
        for (int j = 0; j < 2; j++) {                                                  \
            int row = cprow + 64 * j;                                                  \
            uint32_t d = SW128((uint32_t)(row * 128 + cpkc * 16));                     \
            const __nv_bfloat16* ahs = g_Ahi + (size_t)(m0 + row) * DN + k0 + cpkc * 8;       \
            const __nv_bfloat16* als = g_Alo + (size_t)(m0 + row) * DN + k0 + cpkc * 8;       \
            const __nv_bfloat16* ahb = g_Ahi + (size_t)(BN + m0 + row) * DN + k0 + cpkc * 8;  \
            const __nv_bfloat16* alb = g_Alo + (size_t)(BN + m0 + row) * DN + k0 + cpkc * 8;  \
            const __nv_bfloat16* bh  = g_Bhi + (size_t)(n0 + row) * DN + k0 + cpkc * 8;       \
            const __nv_bfloat16* bl  = g_Blo + (size_t)(n0 + row) * DN + k0 + cpkc * 8;       \
            cp16(st + d, ahs);                                                         \
            cp16(st + 16384 + d, als);                                                 \
            cp16(st + 32768 + d, ahb);                                                 \
            cp16(st + 49152 + d, alb);                                                 \
            cp16(st + 65536 + d, bh);                                                  \
            cp16(st + 81920 + d, bl);                                                  \
        }                                                                              \
        cp_commit();                                                                   \
    }

#define COMPUTE(s)                                                                     \
    {                                                                                  \
        uint32_t st = sb + (s) * STAGE_STRIDE;                                         \
        uint32_t stBh = st + 65536;                                                    \
        uint32_t stBl = st + 81920;                                                    \
        const int arow = warp_m * 32 + (lane & 15);                                    \
        const int acolb = (lane >> 4) << 4;                                            \
        const int brow = warp_n * 32 + (lane & 7) + ((lane >> 4) << 3);                \
        const int bcolb = ((lane >> 3) & 1) << 4;                                      \
        _Pragma("unroll")                                                              \
        for (int ks = 0; ks < 4; ks++) {                                               \
            uint32_t bh[4][2], bl[4][2];                                               \
            _Pragma("unroll")                                                          \
            for (int h = 0; h < 2; h++) {                                              \
                uint32_t off = SW128((uint32_t)((brow + h * 16) * 128 + ks * 32 + bcolb)); \
                uint32_t r0, r1, r2, r3;                                               \
                ldsm_x4(stBh + off, r0, r1, r2, r3);                                   \
                bh[h*2][0] = r0; bh[h*2][1] = r1; bh[h*2+1][0] = r2; bh[h*2+1][1] = r3;\
                ldsm_x4(stBl + off, r0, r1, r2, r3);                                   \
                bl[h*2][0] = r0; bl[h*2][1] = r1; bl[h*2+1][0] = r2; bl[h*2+1][1] = r3;\
            }                                                                          \
            _Pragma("unroll")                                                          \
            for (int z = 0; z < 2; z++) {                                              \
                uint32_t stAh = st + z * 32768;                                        \
                uint32_t stAl = stAh + 16384;                                          \
                _Pragma("unroll")                                                      \
                for (int mf = 0; mf < 2; mf++) {                                       \
                    uint32_t ah0, ah1, ah2, ah3, al0, al1, al2, al3;                   \
                    uint32_t off = SW128((uint32_t)((arow + mf * 16) * 128 + ks * 32 + acolb)); \
                    ldsm_x4(stAh + off, ah0, ah1, ah2, ah3);                           \
                    ldsm_x4(stAl + off, al0, al1, al2, al3);                           \
                    _Pragma("unroll")                                                  \
                    for (int nf = 0; nf < 4; nf++) {                                   \
                        mma_bf16(acc[z][mf][nf][0], acc[z][mf][nf][1], acc[z][mf][nf][2], acc[z][mf][nf][3], \
                                 ah0, ah1, ah2, ah3, bh[nf][0], bh[nf][1]);            \
                        mma_bf16(acc[z][mf][nf][0], acc[z][mf][nf][1], acc[z][mf][nf][2], acc[z][mf][nf][3], \
                                 ah0, ah1, ah2, ah3, bl[nf][0], bl[nf][1]);            \
                        mma_bf16(acc[z][mf][nf][0], acc[z][mf][nf][1], acc[z][mf][nf][2], acc[z][mf][nf][3], \
                                 al0, al1, al2, al3, bh[nf][0], bh[nf][1]);            \
                    }                                                                  \
                }                                                                      \
            }                                                                          \
        }                                                                              \
    }

    ISSUE(0, 0);
    ISSUE(1, 1);

    cp_wait<1>(); __syncthreads();
    COMPUTE(0);  __syncthreads();
    ISSUE(2, 0);

    cp_wait<1>(); __syncthreads();
    COMPUTE(1);  __syncthreads();
    ISSUE(3, 1);

    cp_wait<1>(); __syncthreads();
    COMPUTE(0);  __syncthreads();

    cp_wait<0>(); __syncthreads();
    COMPUTE(1);

    const int gr = lane >> 2;
    const int gc = (lane & 3) * 2;
#pragma unroll
    for (int z = 0; z < 2; z++) {
        float* outp = (z == 0) ? g_score : g_sims;
#pragma unroll
        for (int mf = 0; mf < 2; mf++) {
#pragma unroll
            for (int nf = 0; nf < 4; nf++) {
                int r0 = m0 + warp_m * 32 + mf * 16 + gr;
                int col = n0 + warp_n * 32 + nf * 8 + gc;
                float2 v0 = make_float2(acc[z][mf][nf][0], acc[z][mf][nf][1]);
                float2 v1 = make_float2(acc[z][mf][nf][2], acc[z][mf][nf][3]);
                *(float2*)(outp + (size_t)r0 * PN + col)       = v0;
                *(float2*)(outp + (size_t)(r0 + 8) * PN + col) = v1;
            }
        }
    }
}

// warp0-only: exact 50th-largest of 512 shared values via key bisection.
__device__ __forceinline__ void warp0_pivot(const float* tmax, int t,
                                            unsigned* sh_pk, float* sh_gm) {
    if (t < 32) {
        float m16[16];
#pragma unroll
        for (int k = 0; k < 16; k++) m16[k] = tmax[t + 32 * k];
        float gm = m16[0];
#pragma unroll
        for (int k = 1; k < 16; k++) gm = fmaxf(gm, m16[k]);
        for (int o = 16; o > 0; o >>= 1) gm = fmaxf(gm, __shfl_xor_sync(0xffffffffu, gm, o));
        unsigned klo = 0u, khi = fkey(gm);
#pragma unroll 1
        for (int it = 0; it < 32; it++) {
            if (khi - klo <= 1u) break;
            unsigned mid = klo + ((khi - klo) >> 1);
            float pm = unfkey(mid);
            int c = 0;
#pragma unroll
            for (int k = 0; k < 16; k++) c += (m16[k] > pm);
            for (int o = 16; o > 0; o >>= 1) c += __shfl_xor_sync(0xffffffffu, c, o);
            if (c >= BGK) klo = mid; else khi = mid;
        }
        if (t == 0) { *sh_pk = klo; *sh_gm = gm; }
    }
    __syncthreads();
}

// ---------------- merged loss kernel: blocks [0,256) = A, [256,512) = B ----
__global__ __launch_bounds__(512) void k_loss(const int* __restrict__ cams) {
    __shared__ float s16[16];
    __shared__ int   si16[16];
    __shared__ float tmax[512];
    __shared__ float candv[CAP];
    __shared__ int   candi[CAP];
    __shared__ float sposv[8];
    __shared__ float s_cv[8][16];
    __shared__ int   s_ci[8][16];
    __shared__ int   chos[3];
    __shared__ int   fin[64];
    __shared__ unsigned sh_pk;
    __shared__ float sh_gm;
    __shared__ unsigned sh_cnt, sh_nf;

    const int t = threadIdx.x;
    const int lane = t & 31, wid = t >> 5;

    if (blockIdx.x < BN) {
        // ================= lossA: intra + cross on score =================
        const int b = blockIdx.x;
        const float* ri = g_score + (size_t)b * PN;
        const int pseudo = g_pseudo[b];
        const int cam = cams[b];

        if (t == 0) sh_cnt = 0;
        if (t < 8) sposv[t] = KSCALE * ri[pseudo * 8 + t];

        float v[64];
        float vcam[8];
#pragma unroll
        for (int i = 0; i < 8; i++) {
            int chunk = t + 512 * i;
            const float4* p4 = (const float4*)(ri + 8 * chunk);
            float4 a = p4[0], c = p4[1];
            a.x *= KSCALE; a.y *= KSCALE; a.z *= KSCALE; a.w *= KSCALE;
            c.x *= KSCALE; c.y *= KSCALE; c.z *= KSCALE; c.w *= KSCALE;
            float sel = (cam < 4) ? ((cam < 2) ? (cam == 0 ? a.x : a.y)
                                               : (cam == 2 ? a.z : a.w))
                                  : ((cam < 6) ? (cam == 4 ? c.x : c.y)
                                               : (cam == 6 ? c.z : c.w));
            vcam[i] = sel;
            bool grp = (chunk == pseudo);
            float ninf = NEG_INF;
            v[i*8+0] = grp ? ninf : a.x; v[i*8+1] = grp ? ninf : a.y;
            v[i*8+2] = grp ? ninf : a.z; v[i*8+3] = grp ? ninf : a.w;
            v[i*8+4] = grp ? ninf : c.x; v[i*8+5] = grp ? ninf : c.y;
            v[i*8+6] = grp ? ninf : c.z; v[i*8+7] = grp ? ninf : c.w;
        }

        float m = v[0];
#pragma unroll
        for (int s = 1; s < 64; s++) m = fmaxf(m, v[s]);
        tmax[t] = m;
        float mi = vcam[0];
#pragma unroll
        for (int i = 1; i < 8; i++) mi = fmaxf(mi, vcam[i]);
        float Mi = blockMaxF(mi, s16, t);
        __syncthreads();

        warp0_pivot(tmax, t, &sh_pk, &sh_gm);
        unsigned pk = sh_pk;
        float Mex = sh_gm;
        float M = Mex;
#pragma unroll
        for (int k = 0; k < 8; k++) M = fmaxf(M, sposv[k]);

        float pf = unfkey(pk);
        {
            int c = 0;
#pragma unroll
            for (int s = 0; s < 64; s++) c += (v[s] > pf);
            int tot = blockSumI(c, si16, t);
            unsigned pkhi = fkey(Mex);
#pragma unroll 1
            while (tot > CAP && pkhi - pk > 1u) {
                unsigned mid = pk + ((pkhi - pk) >> 1);
                float pm = unfkey(mid);
                int c2 = 0;
#pragma unroll
                for (int s = 0; s < 64; s++) c2 += (v[s] > pm);
                int t2 = blockSumI(c2, si16, t);
                if (t2 >= BGK) { pk = mid; tot = t2; }
                else pkhi = mid;
            }
            pf = unfkey(pk);
        }

#pragma unroll
        for (int s = 0; s < 64; s++) {
            if (v[s] > pf) {
                unsigned k = atomicAdd(&sh_cnt, 1u);
                if (k < (unsigned)CAP) candv[k] = v[s];
            }
        }
        __syncthreads();
        int nc = (int)min(sh_cnt, (unsigned)CAP);

        float seC = 0.f;
        for (int i = t; i < nc; i += 512) {
            float x = candv[i];
            int r = 0;
            for (int j = 0; j < nc; j++) {
                float w = candv[j];
                r += (w > x) || (w == x && j < i);
            }
            if (r < BGK) seC += __expf(x - M);
        }
        if (t < 8) seC += __expf(sposv[t] - M);
        float sumC = blockSumF(seC, s16, t);

        float seI = 0.f;
#pragma unroll
        for (int i = 0; i < 8; i++) seI += __expf(vcam[i] - Mi);
        float sumI = blockSumF(seI, s16, t);

        if (t == 0) {
            float psum = 0.f;
            for (int k = 0; k < 8; k++) psum += sposv[k];
            g_loss[b]      = Mi + logf(sumI) - sposv[cam];
            g_loss[BN + b] = M  + logf(sumC) - psum * 0.125f;
        }
    } else {
        // ================= lossB: online on sims =================
        const int b = blockIdx.x - BN;
        const float* rsm = g_sims  + (size_t)b * PN;
        const float* rsc = g_score + (size_t)b * PN;

        if (t == 0) { sh_cnt = 0; sh_nf = 3; }

        float v[64];
        float bv[8]; int bi[8];
#pragma unroll
        for (int j = 0; j < 8; j++) { bv[j] = NEG_INF; bi[j] = 0x7fffffff; }
#pragma unroll
        for (int i = 0; i < 8; i++) {
            int chunk = t + 512 * i;
            const float4* p4 = (const float4*)(rsm + 8 * chunk);
            float4 a = p4[0], c = p4[1];
            v[i*8+0]=a.x; v[i*8+1]=a.y; v[i*8+2]=a.z; v[i*8+3]=a.w;
            v[i*8+4]=c.x; v[i*8+5]=c.y; v[i*8+6]=c.z; v[i*8+7]=c.w;
#pragma unroll
            for (int j = 0; j < 8; j++) {
                float x = v[i*8+j];
                if (x > bv[j]) { bv[j] = x; bi[j] = 8 * chunk + j; }
            }
        }

#pragma unroll
        for (int j = 0; j < 8; j++) {
            float x = bv[j]; int idx = bi[j];
            for (int o = 16; o > 0; o >>= 1) {
                float ov = __shfl_down_sync(0xffffffffu, x, o);
                int   oi = __shfl_down_sync(0xffffffffu, idx, o);
                if (ov > x || (ov == x && oi < idx)) { x = ov; idx = oi; }
            }
            if (lane == 0) { s_cv[j][wid] = x; s_ci[j][wid] = idx; }
        }
        __syncthreads();
        if (t == 0) {
            float cv[8]; int ci[8];
            for (int c = 0; c < 8; c++) {
                float bvv = NEG_INF; int bii = 0x7fffffff;
                for (int w2 = 0; w2 < 16; w2++) {
                    float x = s_cv[c][w2]; int idx = s_ci[c][w2];
                    if (x > bvv || (x == bvv && idx < bii)) { bvv = x; bii = idx; }
                }
                cv[c] = bvv; ci[c] = bii;
            }
            bool used[8] = {false,false,false,false,false,false,false,false};
            for (int k = 0; k < PKK; k++) {
                int bc = -1; float bvv = NEG_INF;
                for (int c = 0; c < 8; c++)
                    if (!used[c] && cv[c] > bvv) { bvv = cv[c]; bc = c; }
                used[bc] = true;
                chos[k] = ci[bc];
            }
            fin[0] = chos[0]; fin[1] = chos[1]; fin[2] = chos[2];
        }
        __syncthreads();
        int c0 = chos[0], c1 = chos[1], c2 = chos[2];

#pragma unroll 1
        for (int k = 0; k < 3; k++) {
            int ck = (k == 0) ? c0 : (k == 1 ? c1 : c2);
            if (((ck >> 3) & 511) == t) {
                int slot = ((ck >> 3) >> 9) * 8 + (ck & 7);
#pragma unroll
                for (int s = 0; s < 64; s++)
                    if (s == slot) v[s] = NEG_INF;
            }
        }

        float m = v[0];
#pragma unroll
        for (int s = 1; s < 64; s++) m = fmaxf(m, v[s]);
        tmax[t] = m;
        __syncthreads();
        warp0_pivot(tmax, t, &sh_pk, &sh_gm);
        unsigned pk = sh_pk;
        float pf = unfkey(pk);
        {
            int c = 0;
#pragma unroll
            for (int s = 0; s < 64; s++) c += (v[s] > pf);
            int tot = blockSumI(c, si16, t);
            unsigned pkhi = fkey(sh_gm);
#pragma unroll 1
            while (tot > CAP && pkhi - pk > 1u) {
                unsigned mid = pk + ((pkhi - pk) >> 1);
                float pm = unfkey(mid);
                int c2 = 0;
#pragma unroll
                for (int s = 0; s < 64; s++) c2 += (v[s] > pm);
                int t2 = blockSumI(c2, si16, t);
                if (t2 >= BGK) { pk = mid; tot = t2; }
                else pkhi = mid;
            }
            pf = unfkey(pk);
        }
#pragma unroll
        for (int s = 0; s < 64; s++) {
            if (v[s] > pf) {
                unsigned k = atomicAdd(&sh_cnt, 1u);
                if (k < (unsigned)CAP) {
                    candv[k] = v[s];
                    candi[k] = 8 * (t + 512 * (s >> 3)) + (s & 7);
                }
            }
        }
        __syncthreads();
        int nc = (int)min(sh_cnt, (unsigned)CAP);

        for (int i = t; i < nc; i += 512) {
            float x = candv[i]; int pi = candi[i];
            int r = 0;
            for (int j = 0; j < nc; j++) {
                float w = candv[j];
                r += (w > x) || (w == x && candi[j] < pi);
            }
            if (r < BGK) {
                unsigned k = atomicAdd(&sh_nf, 1u);
                if (k < 64u) fin[k] = pi;
            }
        }
        __syncthreads();
        int nf = (int)min(sh_nf, 64u);   // 53

        float val = (t < nf) ? KSCALE * rsc[fin[t]] : NEG_INF;
        float mo = blockMaxF(val, s16, t);
        float e  = (t < nf) ? __expf(val - mo) : 0.f;
        float se = blockSumF(e, s16, t);
        if (t == 0) {
            float csum = KSCALE * rsc[c0] + KSCALE * rsc[c1] + KSCALE * rsc[c2];
            g_loss[2 * BN + b] = mo + logf(se) - csum * (1.0f / 3.0f);
        }
    }
}

// ---------------- final reduction ----------------
__global__ void k_final(const int* __restrict__ cams, float* __restrict__ out) {
    __shared__ float sv[256];
    __shared__ int   sc[256];
    __shared__ float s8[8];
    int t = threadIdx.x;
    sv[t] = g_loss[t] + g_loss[BN + t] + g_loss[2 * BN + t];
    sc[t] = cams[t];
    __syncthreads();
    if (t < 8) {
        float acc = 0.f; int n = 0;
        for (int b = 0; b < BN; b++)
            if (sc[b] == t) { acc += sv[b]; n++; }
        s8[t] = (n > 0) ? acc / (float)n : 0.f;
    }
    __syncthreads();
    if (t == 0) {
        float tot = 0.f;
        for (int c = 0; c < 8; c++) tot += s8[c];
        out[0] = tot;
    }
}

// ---------------- launch ----------------
extern "C" void kernel_launch(void* const* d_in, const int* in_sizes, int n_in,
                              void* d_out, int out_size) {
    const float* features        = (const float*)d_in[0];
    const int*   targets         = (const int*)d_in[1];
    const int*   cams            = (const int*)d_in[2];
    const float* global_memory   = (const float*)d_in[4];
    const int*   all_proxy_label = (const int*)d_in[6];
    float* out = (float*)d_out;

    cudaFuncSetAttribute(k_gemm_mma, cudaFuncAttributeMaxDynamicSharedMemorySize, SMEM_GEMM);

    k_prep<<<1024 + BN, 256>>>(features, targets, all_proxy_label, global_memory);
    dim3 gg(PN / 128, 2);
    k_gemm_mma<<<gg, 512, SMEM_GEMM>>>();
    k_loss<<<2 * BN, 512>>>(cams);
    k_final<<<1, 256>>>(cams, out);
}